// round 4
// baseline (speedup 1.0000x reference)
#include <cuda_runtime.h>
#include <math.h>

// Problem constants (B=4, S=2048, D=2048, H=16, Dh=128)
#define BB    4
#define SS    2048
#define DD    2048
#define HH    16
#define DH    128
#define MM    (BB * SS)        // 8192 rows
#define NQKV  (3 * DD)         // 6144

// Scratch: __device__ globals (allocation-guard-safe)
__device__ float g_Xn [(size_t)MM * DD];     //  64 MB LayerNorm output
__device__ float g_QKV[(size_t)MM * NQKV];   // 192 MB Q|K|V (RoPE applied in place)
__device__ float g_ctx[(size_t)MM * DD];     //  64 MB attention context

// ---------------------------------------------------------------------------
// Kernel 1: LayerNorm. One block per row (D=2048), 256 threads, float4 I/O.
// ---------------------------------------------------------------------------
__global__ void __launch_bounds__(256) ln_kernel(
    const float* __restrict__ X, const float* __restrict__ w,
    const float* __restrict__ b, float* __restrict__ Xn)
{
    const int row = blockIdx.x;
    const int t   = threadIdx.x;
    const float4* xr = (const float4*)(X + (size_t)row * DD);

    float4 v0 = xr[t];
    float4 v1 = xr[t + 256];

    float s  = v0.x + v0.y + v0.z + v0.w + v1.x + v1.y + v1.z + v1.w;
    float sq = v0.x*v0.x + v0.y*v0.y + v0.z*v0.z + v0.w*v0.w
             + v1.x*v1.x + v1.y*v1.y + v1.z*v1.z + v1.w*v1.w;

    #pragma unroll
    for (int off = 16; off > 0; off >>= 1) {
        s  += __shfl_xor_sync(0xffffffffu, s,  off);
        sq += __shfl_xor_sync(0xffffffffu, sq, off);
    }
    __shared__ float sm[8], sm2[8];
    const int warp = t >> 5, lane = t & 31;
    if (lane == 0) { sm[warp] = s; sm2[warp] = sq; }
    __syncthreads();
    float S = 0.f, SQ = 0.f;
    #pragma unroll
    for (int i = 0; i < 8; i++) { S += sm[i]; SQ += sm2[i]; }

    const float mu  = S * (1.f / (float)DD);
    const float var = SQ * (1.f / (float)DD) - mu * mu;
    const float inv = rsqrtf(var + 1e-5f);

    const float4* wv = (const float4*)w;
    const float4* bv = (const float4*)b;
    float4 w0 = wv[t], w1 = wv[t + 256];
    float4 b0 = bv[t], b1 = bv[t + 256];

    float4 o0, o1;
    o0.x = (v0.x - mu) * inv * w0.x + b0.x;
    o0.y = (v0.y - mu) * inv * w0.y + b0.y;
    o0.z = (v0.z - mu) * inv * w0.z + b0.z;
    o0.w = (v0.w - mu) * inv * w0.w + b0.w;
    o1.x = (v1.x - mu) * inv * w1.x + b1.x;
    o1.y = (v1.y - mu) * inv * w1.y + b1.y;
    o1.z = (v1.z - mu) * inv * w1.z + b1.z;
    o1.w = (v1.w - mu) * inv * w1.w + b1.w;

    float4* outr = (float4*)(Xn + (size_t)row * DD);
    outr[t]       = o0;
    outr[t + 256] = o1;
}

// ---------------------------------------------------------------------------
// Kernel 2: fp32 SGEMM  C[M,N] = A[M,K] @ B[K,N]  (+ residual R if ADD)
// 128x128 block tile, BK=16, 256 threads, 8x8 per-thread microtile.
// All dims are exact multiples (M=8192, N in {6144,2048}, K=2048).
// ---------------------------------------------------------------------------
template<int ADD>
__global__ void __launch_bounds__(256) sgemm_kernel(
    const float* __restrict__ A, const float* __restrict__ Bm,
    const float* __restrict__ R, float* __restrict__ C,
    int M, int N, int K)
{
    __shared__ float As[16][132];   // transposed tile, pad 132 -> ~2-way STS worst case
    __shared__ float Bs[16][128];

    const int tid = threadIdx.x;
    const int tx  = tid & 15, ty = tid >> 4;
    const int bm  = blockIdx.y * 128;
    const int bn  = blockIdx.x * 128;

    float acc[8][8];
    #pragma unroll
    for (int i = 0; i < 8; i++)
        #pragma unroll
        for (int j = 0; j < 8; j++) acc[i][j] = 0.f;

    for (int k0 = 0; k0 < K; k0 += 16) {
        // A tile: 128 rows x 16 cols = 512 float4 (4 per row), coalesced reads
        #pragma unroll
        for (int u = 0; u < 2; u++) {
            int f  = tid + u * 256;
            int r  = f >> 2;
            int c4 = (f & 3) << 2;
            float4 a = *(const float4*)(A + (size_t)(bm + r) * K + k0 + c4);
            As[c4 + 0][r] = a.x;
            As[c4 + 1][r] = a.y;
            As[c4 + 2][r] = a.z;
            As[c4 + 3][r] = a.w;
        }
        // B tile: 16 rows x 128 cols, fully coalesced float4
        #pragma unroll
        for (int u = 0; u < 2; u++) {
            int f  = tid + u * 256;
            int r  = f >> 5;
            int c4 = (f & 31) << 2;
            *(float4*)(&Bs[r][c4]) =
                *(const float4*)(Bm + (size_t)(k0 + r) * N + bn + c4);
        }
        __syncthreads();

        #pragma unroll
        for (int kk = 0; kk < 16; kk++) {
            float a[8], b[8];
            #pragma unroll
            for (int i = 0; i < 8; i++) a[i] = As[kk][ty * 8 + i];
            *(float4*)(b)     = *(const float4*)(&Bs[kk][tx * 8]);
            *(float4*)(b + 4) = *(const float4*)(&Bs[kk][tx * 8 + 4]);
            #pragma unroll
            for (int i = 0; i < 8; i++)
                #pragma unroll
                for (int j = 0; j < 8; j++)
                    acc[i][j] = fmaf(a[i], b[j], acc[i][j]);
        }
        __syncthreads();
    }

    #pragma unroll
    for (int i = 0; i < 8; i++) {
        size_t off = (size_t)(bm + ty * 8 + i) * N + bn + tx * 8;
        float4 o0 = make_float4(acc[i][0], acc[i][1], acc[i][2], acc[i][3]);
        float4 o1 = make_float4(acc[i][4], acc[i][5], acc[i][6], acc[i][7]);
        if (ADD) {
            float4 r0 = *(const float4*)(R + off);
            float4 r1 = *(const float4*)(R + off + 4);
            o0.x += r0.x; o0.y += r0.y; o0.z += r0.z; o0.w += r0.w;
            o1.x += r1.x; o1.y += r1.y; o1.z += r1.z; o1.w += r1.w;
        }
        *(float4*)(C + off)     = o0;
        *(float4*)(C + off + 4) = o1;
    }
}

// ---------------------------------------------------------------------------
// Kernel 3: RoPE in place on Q and K sections of QKV.
// lucidrains convention: rotate first Dh/2=64 channels as interleaved pairs,
// pass channels 64..127 through. inv_freq[p] = 10000^(-p/32), p = 0..31.
// One thread per (row, section, head, pair): 8192*2*16*32 = 8,388,608 threads.
// ---------------------------------------------------------------------------
__global__ void __launch_bounds__(256) rope_kernel(float* __restrict__ QKV)
{
    const int idx = blockIdx.x * blockDim.x + threadIdx.x;
    const int total = MM * 2 * HH * 32;
    if (idx >= total) return;

    const int pair = idx & 31;
    const int head = (idx >> 5) & 15;
    const int sec  = (idx >> 9) & 1;          // 0 = Q, 1 = K
    const int row  = idx >> 10;
    const int s    = row & (SS - 1);          // position within sequence

    // inv_freq = exp(-ln(10000) * pair / 32)
    const float inv = expf(-9.210340371976184f * ((float)pair * (1.f / 32.f)));
    const float ang = (float)s * inv;
    float sn, cs;
    sincosf(ang, &sn, &cs);

    const size_t base = (size_t)row * NQKV + sec * DD + head * DH + pair * 2;
    const float x1 = QKV[base];
    const float x2 = QKV[base + 1];
    QKV[base]     = x1 * cs - x2 * sn;
    QKV[base + 1] = x2 * cs + x1 * sn;
}

// ---------------------------------------------------------------------------
// Kernel 4: fp32 flash attention. Block = (q-tile 32, head, batch), 256 thr.
// Static smem ~37.5 KB (no opt-in needed). Online softmax, Dh=128.
// ---------------------------------------------------------------------------
#define AQ 32
#define AK 32

__global__ void __launch_bounds__(256) attn_kernel(
    const float* __restrict__ QKV, float* __restrict__ ctx)
{
    __shared__ float Qs [AQ][DH + 1];   // stride 129: conflict-free
    __shared__ float KVs[AK][DH + 1];   // holds K, then V, per tile
    __shared__ float Ssm[AQ][AK + 1];   // stride 33: conflict-free
    __shared__ float row_m[AQ], row_l[AQ], row_f[AQ];

    const int t  = threadIdx.x;
    const int qt = blockIdx.x;   // q tile   (0..63)
    const int h  = blockIdx.y;   // head     (0..15)
    const int b  = blockIdx.z;   // batch    (0..3)

    const float scale = 0.08838834764831845f;  // 1/sqrt(128)

    // Load Q tile (scaled). 32*128 floats, 16 per thread, coalesced.
    #pragma unroll
    for (int j = 0; j < 16; j++) {
        int idx = t + j * 256;
        int r = idx >> 7, c = idx & 127;
        Qs[r][c] = QKV[(size_t)(b * SS + qt * AQ + r) * NQKV + h * DH + c] * scale;
    }
    if (t < AQ) { row_m[t] = -INFINITY; row_l[t] = 0.f; }

    // PV / output ownership: 2 q-rows x 8 d-cols per thread
    const int qp = t & 15;            // q pair index
    const int q0 = qp * 2;
    const int d0 = (t >> 4) * 8;      // d offset (16 groups x 8 = 128)
    float o[2][8];
    #pragma unroll
    for (int i = 0; i < 8; i++) { o[0][i] = 0.f; o[1][i] = 0.f; }

    // Score microtile ownership: 2x2 per thread (16x16 thread grid)
    const int stx = t & 15, sty = t >> 4;
    const int qa = sty * 2, ka = stx * 2;

    __syncthreads();

    for (int kt = 0; kt < SS / AK; kt++) {
        // --- load K tile ---
        #pragma unroll
        for (int j = 0; j < 16; j++) {
            int idx = t + j * 256;
            int r = idx >> 7, c = idx & 127;
            KVs[r][c] = QKV[(size_t)(b * SS + kt * AK + r) * NQKV + DD + h * DH + c];
        }
        __syncthreads();

        // --- scores: S = Q * K^T (2x2 microtile) ---
        {
            float s00 = 0.f, s01 = 0.f, s10 = 0.f, s11 = 0.f;
            #pragma unroll 8
            for (int d = 0; d < DH; d++) {
                float a0 = Qs[qa][d],     a1 = Qs[qa + 1][d];
                float b0 = KVs[ka][d],    b1 = KVs[ka + 1][d];
                s00 = fmaf(a0, b0, s00);  s01 = fmaf(a0, b1, s01);
                s10 = fmaf(a1, b0, s10);  s11 = fmaf(a1, b1, s11);
            }
            Ssm[qa][ka]         = s00;
            Ssm[qa][ka + 1]     = s01;
            Ssm[qa + 1][ka]     = s10;
            Ssm[qa + 1][ka + 1] = s11;
        }
        __syncthreads();

        // --- load V tile (overwrites KVs; K reads completed above) ---
        #pragma unroll
        for (int j = 0; j < 16; j++) {
            int idx = t + j * 256;
            int r = idx >> 7, c = idx & 127;
            KVs[r][c] = QKV[(size_t)(b * SS + kt * AK + r) * NQKV + 2 * DD + h * DH + c];
        }

        // --- online softmax (one thread per q row) ---
        if (t < AQ) {
            const int r = t;
            float m_old = row_m[r];
            float mx = m_old;
            #pragma unroll
            for (int k = 0; k < AK; k++) mx = fmaxf(mx, Ssm[r][k]);
            float f = (m_old == -INFINITY) ? 0.f : __expf(m_old - mx);
            float sum = 0.f;
            #pragma unroll
            for (int k = 0; k < AK; k++) {
                float p = __expf(Ssm[r][k] - mx);
                Ssm[r][k] = p;
                sum += p;
            }
            row_l[r] = row_l[r] * f + sum;
            row_m[r] = mx;
            row_f[r] = f;
        }
        __syncthreads();

        // --- accumulate O = O*f + P @ V ---
        {
            const float f0 = row_f[q0], f1 = row_f[q0 + 1];
            #pragma unroll
            for (int i = 0; i < 8; i++) { o[0][i] *= f0; o[1][i] *= f1; }
            #pragma unroll 4
            for (int k = 0; k < AK; k++) {
                float p0 = Ssm[q0][k], p1 = Ssm[q0 + 1][k];
                #pragma unroll
                for (int i = 0; i < 8; i++) {
                    float v = KVs[k][d0 + i];
                    o[0][i] = fmaf(p0, v, o[0][i]);
                    o[1][i] = fmaf(p1, v, o[1][i]);
                }
            }
        }
        __syncthreads();
    }

    // --- epilogue: normalize and write ctx (B,S,H*Dh) row-major ---
    const float inv0 = 1.f / row_l[q0];
    const float inv1 = 1.f / row_l[q0 + 1];
    size_t base0 = (size_t)(b * SS + qt * AQ + q0) * DD + h * DH + d0;
    size_t base1 = base0 + DD;
    #pragma unroll
    for (int i = 0; i < 8; i++) {
        ctx[base0 + i] = o[0][i] * inv0;
        ctx[base1 + i] = o[1][i] * inv1;
    }
}

// ---------------------------------------------------------------------------
// Launch. Inputs (metadata order): X, ln_w, ln_b, W_in, W_out. Output fp32.
// Default-stream kernel launches only -> graph-capturable, allocation-free.
// ---------------------------------------------------------------------------
extern "C" void kernel_launch(void* const* d_in, const int* in_sizes, int n_in,
                              void* d_out, int out_size)
{
    const float* X     = (const float*)d_in[0];
    const float* ln_w  = (const float*)d_in[1];
    const float* ln_b  = (const float*)d_in[2];
    const float* W_in  = (const float*)d_in[3];
    const float* W_out = (const float*)d_in[4];
    float*       out   = (float*)d_out;

    float *pXn, *pQKV, *pCtx;
    cudaGetSymbolAddress((void**)&pXn,  g_Xn);
    cudaGetSymbolAddress((void**)&pQKV, g_QKV);
    cudaGetSymbolAddress((void**)&pCtx, g_ctx);

    // 1) LayerNorm
    ln_kernel<<<MM, 256>>>(X, ln_w, ln_b, pXn);

    // 2) QKV projection: [8192,2048] @ [2048,6144]
    sgemm_kernel<0><<<dim3(NQKV / 128, MM / 128), 256>>>(
        pXn, W_in, nullptr, pQKV, MM, NQKV, DD);

    // 3) RoPE on Q and K sections
    {
        const int total = MM * 2 * HH * 32;   // 8,388,608
        rope_kernel<<<(total + 255) / 256, 256>>>(pQKV);
    }

    // 4) Attention (flash, fp32)
    attn_kernel<<<dim3(SS / AQ, HH, BB), 256>>>(pQKV, pCtx);

    // 5) Output projection + residual: [8192,2048] @ [2048,2048] + X
    sgemm_kernel<1><<<dim3(DD / 128, MM / 128), 256>>>(
        pCtx, W_out, X, out, MM, DD, DD);
}

// round 7
// speedup vs baseline: 1.3058x; 1.3058x over previous
#include <cuda_runtime.h>
#include <cuda_bf16.h>
#include <math.h>
#include <stdint.h>

// Problem constants (B=4, S=2048, D=2048, H=16, Dh=128)
#define BB    4
#define SS    2048
#define DD    2048
#define HH    16
#define DH    128
#define MM    (BB * SS)        // 8192 rows
#define NQKV  (3 * DD)         // 6144
#define GK    2048             // GEMM inner K (per segment)

// ---------------------------------------------------------------------------
// Scratch: __device__ globals (allocation-guard-safe)
// ---------------------------------------------------------------------------
__device__ float          g_QKV  [(size_t)MM * NQKV];   // 192 MB fp32 Q|K|V
__device__ __nv_bfloat16  g_Ahi  [(size_t)MM * DD];
__device__ __nv_bfloat16  g_Alo  [(size_t)MM * DD];
__device__ __nv_bfloat16  g_Whi  [(size_t)NQKV * DD];   // W_in^T  [6144][2048]
__device__ __nv_bfloat16  g_Wlo  [(size_t)NQKV * DD];
__device__ __nv_bfloat16  g_WoHi [(size_t)DD * DD];     // W_out^T [2048][2048]
__device__ __nv_bfloat16  g_WoLo [(size_t)DD * DD];
__device__ __nv_bfloat16  g_CtxHi[(size_t)MM * DD];
__device__ __nv_bfloat16  g_CtxLo[(size_t)MM * DD];

// ---------------------------------------------------------------------------
// Kernel 1: LayerNorm -> bf16 hi/lo split
// ---------------------------------------------------------------------------
__global__ void __launch_bounds__(256) ln_kernel(
    const float* __restrict__ X, const float* __restrict__ w,
    const float* __restrict__ b,
    __nv_bfloat16* __restrict__ Ahi, __nv_bfloat16* __restrict__ Alo)
{
    const int row = blockIdx.x;
    const int t   = threadIdx.x;
    const float4* xr = (const float4*)(X + (size_t)row * DD);

    float4 v0 = xr[t];
    float4 v1 = xr[t + 256];

    float s  = v0.x + v0.y + v0.z + v0.w + v1.x + v1.y + v1.z + v1.w;
    float sq = v0.x*v0.x + v0.y*v0.y + v0.z*v0.z + v0.w*v0.w
             + v1.x*v1.x + v1.y*v1.y + v1.z*v1.z + v1.w*v1.w;

    #pragma unroll
    for (int off = 16; off > 0; off >>= 1) {
        s  += __shfl_xor_sync(0xffffffffu, s,  off);
        sq += __shfl_xor_sync(0xffffffffu, sq, off);
    }
    __shared__ float sm[8], sm2[8];
    const int warp = t >> 5, lane = t & 31;
    if (lane == 0) { sm[warp] = s; sm2[warp] = sq; }
    __syncthreads();
    float S = 0.f, SQ = 0.f;
    #pragma unroll
    for (int i = 0; i < 8; i++) { S += sm[i]; SQ += sm2[i]; }

    const float mu  = S * (1.f / (float)DD);
    const float var = SQ * (1.f / (float)DD) - mu * mu;
    const float inv = rsqrtf(var + 1e-5f);

    const float4* wv = (const float4*)w;
    const float4* bv = (const float4*)b;
    float4 w0 = wv[t], w1 = wv[t + 256];
    float4 b0 = bv[t], b1 = bv[t + 256];

    float y[8];
    y[0] = (v0.x - mu) * inv * w0.x + b0.x;
    y[1] = (v0.y - mu) * inv * w0.y + b0.y;
    y[2] = (v0.z - mu) * inv * w0.z + b0.z;
    y[3] = (v0.w - mu) * inv * w0.w + b0.w;
    y[4] = (v1.x - mu) * inv * w1.x + b1.x;
    y[5] = (v1.y - mu) * inv * w1.y + b1.y;
    y[6] = (v1.z - mu) * inv * w1.z + b1.z;
    y[7] = (v1.w - mu) * inv * w1.w + b1.w;

    __nv_bfloat16* H = Ahi + (size_t)row * DD;
    __nv_bfloat16* L = Alo + (size_t)row * DD;
    #pragma unroll
    for (int g = 0; g < 2; g++) {
        int c0 = (g == 0) ? t * 4 : (t + 256) * 4;
        #pragma unroll
        for (int i = 0; i < 4; i++) {
            float v = y[g * 4 + i];
            __nv_bfloat16 h = __float2bfloat16(v);
            H[c0 + i] = h;
            L[c0 + i] = __float2bfloat16(v - __bfloat162float(h));
        }
    }
}

// ---------------------------------------------------------------------------
// Kernel 2: weight transpose + bf16 hi/lo split.  W[2048][Ncols] fp32
//           -> Whi/Wlo [Ncols][2048] bf16 (K-major rows)
// ---------------------------------------------------------------------------
__global__ void __launch_bounds__(256) wsplit_kernel(
    const float* __restrict__ W,
    __nv_bfloat16* __restrict__ Whi, __nv_bfloat16* __restrict__ Wlo, int Ncols)
{
    __shared__ float ts[32][33];
    const int tx = threadIdx.x & 31, ty = threadIdx.x >> 5;   // 32x8
    const int n0 = blockIdx.x * 32, k0 = blockIdx.y * 32;

    #pragma unroll
    for (int j = 0; j < 4; j++) {
        int r = ty + j * 8;
        ts[r][tx] = W[(size_t)(k0 + r) * Ncols + n0 + tx];
    }
    __syncthreads();
    #pragma unroll
    for (int j = 0; j < 4; j++) {
        int r = ty + j * 8;                  // output n-offset
        float v = ts[tx][r];
        __nv_bfloat16 h = __float2bfloat16(v);
        size_t o = (size_t)(n0 + r) * GK + k0 + tx;
        Whi[o] = h;
        Wlo[o] = __float2bfloat16(v - __bfloat162float(h));
    }
}

// ---------------------------------------------------------------------------
// Kernel 3: bf16-split GEMM on mma.sync (HMMA).
// C[M,N] = A @ B^T, A=[M][2048] (hi/lo), B=[N][2048] K-major (hi/lo).
// fp32 emulation: hi*hi + lo*hi + hi*lo over 3 K-segments.
// Tile 128x128, BK=32, 8 warps x (64x32 warp tile), double-buffered smem.
// ---------------------------------------------------------------------------
#define BK    32
#define ASTR  40                       // padded smem stride in bf16 units
#define NCH   192                      // 3 segments * (2048/32)

#define MMA16816(c, a, b_) \
    asm volatile("mma.sync.aligned.m16n8k16.row.col.f32.bf16.bf16.f32 " \
        "{%0,%1,%2,%3}, {%4,%5,%6,%7}, {%8,%9}, {%0,%1,%2,%3};" \
        : "+f"((c)[0]), "+f"((c)[1]), "+f"((c)[2]), "+f"((c)[3]) \
        : "r"((a)[0]), "r"((a)[1]), "r"((a)[2]), "r"((a)[3]), \
          "r"((b_)[0]), "r"((b_)[1]))

template<int ADD>
__global__ void __launch_bounds__(256, 2) mma_gemm(
    const __nv_bfloat16* __restrict__ Ahi, const __nv_bfloat16* __restrict__ Alo,
    const __nv_bfloat16* __restrict__ Bhi, const __nv_bfloat16* __restrict__ Blo,
    const float* __restrict__ R, float* __restrict__ C, int N)
{
    __shared__ __nv_bfloat16 As[2][128 * ASTR];   // 20480 B
    __shared__ __nv_bfloat16 Bs[2][128 * ASTR];   // 20480 B

    const int tid  = threadIdx.x;
    const int wid  = tid >> 5, lane = tid & 31;
    const int gid  = lane >> 2, tid2 = lane & 3;
    const int wm   = wid & 1;            // 2 m-warps  (64 rows each)
    const int wn   = wid >> 1;           // 4 n-warps  (32 cols each)
    const int bm   = blockIdx.y * 128, bn = blockIdx.x * 128;

    const __nv_bfloat16* Asrc[3] = { Ahi, Alo, Ahi };
    const __nv_bfloat16* Bsrc[3] = { Bhi, Bhi, Blo };

    float acc[4][4][4];
    #pragma unroll
    for (int i = 0; i < 4; i++)
        #pragma unroll
        for (int j = 0; j < 4; j++)
            #pragma unroll
            for (int q = 0; q < 4; q++) acc[i][j][q] = 0.f;

    // gmem->smem mapping: 512 uint4 per tile, 2 per thread
    const int r0 = tid >> 2;             // rows tid/4 and tid/4+64
    const int c8 = (tid & 3) * 8;        // bf16 col offset

    // preload chunk 0 into buffer 0
    {
        *(uint4*)&As[0][ r0       * ASTR + c8] = *(const uint4*)(Asrc[0] + (size_t)(bm + r0     ) * GK + c8);
        *(uint4*)&As[0][(r0 + 64) * ASTR + c8] = *(const uint4*)(Asrc[0] + (size_t)(bm + r0 + 64) * GK + c8);
        *(uint4*)&Bs[0][ r0       * ASTR + c8] = *(const uint4*)(Bsrc[0] + (size_t)(bn + r0     ) * GK + c8);
        *(uint4*)&Bs[0][(r0 + 64) * ASTR + c8] = *(const uint4*)(Bsrc[0] + (size_t)(bn + r0 + 64) * GK + c8);
    }
    __syncthreads();

    for (int kc = 0; kc < NCH; kc++) {
        const int cur = kc & 1;

        // prefetch next chunk into registers
        uint4 ra0, ra1, rb0, rb1;
        if (kc + 1 < NCH) {
            const int seg  = (kc + 1) >> 6;
            const int koff = ((kc + 1) & 63) * BK;
            ra0 = *(const uint4*)(Asrc[seg] + (size_t)(bm + r0     ) * GK + koff + c8);
            ra1 = *(const uint4*)(Asrc[seg] + (size_t)(bm + r0 + 64) * GK + koff + c8);
            rb0 = *(const uint4*)(Bsrc[seg] + (size_t)(bn + r0     ) * GK + koff + c8);
            rb1 = *(const uint4*)(Bsrc[seg] + (size_t)(bn + r0 + 64) * GK + koff + c8);
        }

        // compute on current buffer
        const __nv_bfloat16* Ab = &As[cur][(wm * 64 + gid) * ASTR + tid2 * 2];
        const __nv_bfloat16* Bb = &Bs[cur][(wn * 32 + gid) * ASTR + tid2 * 2];
        #pragma unroll
        for (int ks = 0; ks < BK; ks += 16) {
            uint32_t af[4][4], bf_[4][2];
            #pragma unroll
            for (int mf = 0; mf < 4; mf++) {
                const __nv_bfloat16* p = Ab + mf * 16 * ASTR + ks;
                af[mf][0] = *(const uint32_t*)(p);
                af[mf][1] = *(const uint32_t*)(p + 8 * ASTR);
                af[mf][2] = *(const uint32_t*)(p + 8);
                af[mf][3] = *(const uint32_t*)(p + 8 * ASTR + 8);
            }
            #pragma unroll
            for (int nf = 0; nf < 4; nf++) {
                const __nv_bfloat16* p = Bb + nf * 8 * ASTR + ks;
                bf_[nf][0] = *(const uint32_t*)(p);
                bf_[nf][1] = *(const uint32_t*)(p + 8);
            }
            #pragma unroll
            for (int mf = 0; mf < 4; mf++)
                #pragma unroll
                for (int nf = 0; nf < 4; nf++)
                    MMA16816(acc[mf][nf], af[mf], bf_[nf]);
        }

        // commit prefetched chunk to the other buffer
        if (kc + 1 < NCH) {
            const int nxt = (kc + 1) & 1;
            *(uint4*)&As[nxt][ r0       * ASTR + c8] = ra0;
            *(uint4*)&As[nxt][(r0 + 64) * ASTR + c8] = ra1;
            *(uint4*)&Bs[nxt][ r0       * ASTR + c8] = rb0;
            *(uint4*)&Bs[nxt][(r0 + 64) * ASTR + c8] = rb1;
        }
        __syncthreads();
    }

    // epilogue
    #pragma unroll
    for (int mf = 0; mf < 4; mf++) {
        #pragma unroll
        for (int nf = 0; nf < 4; nf++) {
            const int row = bm + wm * 64 + mf * 16 + gid;
            const int col = bn + wn * 32 + nf * 8 + tid2 * 2;
            size_t o0 = (size_t)row * N + col;
            size_t o1 = (size_t)(row + 8) * N + col;
            float2 v0 = make_float2(acc[mf][nf][0], acc[mf][nf][1]);
            float2 v1 = make_float2(acc[mf][nf][2], acc[mf][nf][3]);
            if (ADD) {
                float2 q0 = *(const float2*)(R + o0);
                float2 q1 = *(const float2*)(R + o1);
                v0.x += q0.x; v0.y += q0.y;
                v1.x += q1.x; v1.y += q1.y;
            }
            *(float2*)(C + o0) = v0;
            *(float2*)(C + o1) = v1;
        }
    }
}

// ---------------------------------------------------------------------------
// Kernel 4: RoPE in place on Q and K sections of QKV (fp32).
// ---------------------------------------------------------------------------
__global__ void __launch_bounds__(256) rope_kernel(float* __restrict__ QKV)
{
    const int idx = blockIdx.x * blockDim.x + threadIdx.x;
    const int total = MM * 2 * HH * 32;
    if (idx >= total) return;

    const int pair = idx & 31;
    const int head = (idx >> 5) & 15;
    const int sec  = (idx >> 9) & 1;          // 0 = Q, 1 = K
    const int row  = idx >> 10;
    const int s    = row & (SS - 1);

    const float inv = expf(-9.210340371976184f * ((float)pair * (1.f / 32.f)));
    const float ang = (float)s * inv;
    float sn, cs;
    sincosf(ang, &sn, &cs);

    const size_t base = (size_t)row * NQKV + sec * DD + head * DH + pair * 2;
    const float x1 = QKV[base];
    const float x2 = QKV[base + 1];
    QKV[base]     = x1 * cs - x2 * sn;
    QKV[base + 1] = x2 * cs + x1 * sn;
}

// ---------------------------------------------------------------------------
// Kernel 5: fp32 flash attention; epilogue emits bf16 hi/lo ctx.
// ---------------------------------------------------------------------------
#define AQ 32
#define AK 32

__global__ void __launch_bounds__(256) attn_kernel(
    const float* __restrict__ QKV,
    __nv_bfloat16* __restrict__ ctxh, __nv_bfloat16* __restrict__ ctxl)
{
    __shared__ float Qs [AQ][DH + 1];
    __shared__ float KVs[AK][DH + 1];
    __shared__ float Ssm[AQ][AK + 1];
    __shared__ float row_m[AQ], row_l[AQ], row_f[AQ];

    const int t  = threadIdx.x;
    const int qt = blockIdx.x;
    const int h  = blockIdx.y;
    const int b  = blockIdx.z;

    const float scale = 0.08838834764831845f;  // 1/sqrt(128)

    #pragma unroll
    for (int j = 0; j < 16; j++) {
        int idx = t + j * 256;
        int r = idx >> 7, c = idx & 127;
        Qs[r][c] = QKV[(size_t)(b * SS + qt * AQ + r) * NQKV + h * DH + c] * scale;
    }
    if (t < AQ) { row_m[t] = -INFINITY; row_l[t] = 0.f; }

    const int qp = t & 15;
    const int q0 = qp * 2;
    const int d0 = (t >> 4) * 8;
    float o[2][8];
    #pragma unroll
    for (int i = 0; i < 8; i++) { o[0][i] = 0.f; o[1][i] = 0.f; }

    const int stx = t & 15, sty = t >> 4;
    const int qa = sty * 2, ka = stx * 2;

    __syncthreads();

    for (int kt = 0; kt < SS / AK; kt++) {
        #pragma unroll
        for (int j = 0; j < 16; j++) {
            int idx = t + j * 256;
            int r = idx >> 7, c = idx & 127;
            KVs[r][c] = QKV[(size_t)(b * SS + kt * AK + r) * NQKV + DD + h * DH + c];
        }
        __syncthreads();

        {
            float s00 = 0.f, s01 = 0.f, s10 = 0.f, s11 = 0.f;
            #pragma unroll 8
            for (int d = 0; d < DH; d++) {
                float a0 = Qs[qa][d],     a1 = Qs[qa + 1][d];
                float b0 = KVs[ka][d],    b1 = KVs[ka + 1][d];
                s00 = fmaf(a0, b0, s00);  s01 = fmaf(a0, b1, s01);
                s10 = fmaf(a1, b0, s10);  s11 = fmaf(a1, b1, s11);
            }
            Ssm[qa][ka]         = s00;
            Ssm[qa][ka + 1]     = s01;
            Ssm[qa + 1][ka]     = s10;
            Ssm[qa + 1][ka + 1] = s11;
        }
        __syncthreads();

        #pragma unroll
        for (int j = 0; j < 16; j++) {
            int idx = t + j * 256;
            int r = idx >> 7, c = idx & 127;
            KVs[r][c] = QKV[(size_t)(b * SS + kt * AK + r) * NQKV + 2 * DD + h * DH + c];
        }

        if (t < AQ) {
            const int r = t;
            float m_old = row_m[r];
            float mx = m_old;
            #pragma unroll
            for (int k = 0; k < AK; k++) mx = fmaxf(mx, Ssm[r][k]);
            float f = (m_old == -INFINITY) ? 0.f : __expf(m_old - mx);
            float sum = 0.f;
            #pragma unroll
            for (int k = 0; k < AK; k++) {
                float p = __expf(Ssm[r][k] - mx);
                Ssm[r][k] = p;
                sum += p;
            }
            row_l[r] = row_l[r] * f + sum;
            row_m[r] = mx;
            row_f[r] = f;
        }
        __syncthreads();

        {
            const float f0 = row_f[q0], f1 = row_f[q0 + 1];
            #pragma unroll
            for (int i = 0; i < 8; i++) { o[0][i] *= f0; o[1][i] *= f1; }
            #pragma unroll 4
            for (int k = 0; k < AK; k++) {
                float p0 = Ssm[q0][k], p1 = Ssm[q0 + 1][k];
                #pragma unroll
                for (int i = 0; i < 8; i++) {
                    float v = KVs[k][d0 + i];
                    o[0][i] = fmaf(p0, v, o[0][i]);
                    o[1][i] = fmaf(p1, v, o[1][i]);
                }
            }
        }
        __syncthreads();
    }

    const float inv0 = 1.f / row_l[q0];
    const float inv1 = 1.f / row_l[q0 + 1];
    size_t base0 = (size_t)(b * SS + qt * AQ + q0) * DD + h * DH + d0;
    size_t base1 = base0 + DD;
    #pragma unroll
    for (int i = 0; i < 8; i++) {
        float v0 = o[0][i] * inv0;
        float v1 = o[1][i] * inv1;
        __nv_bfloat16 h0 = __float2bfloat16(v0);
        __nv_bfloat16 h1 = __float2bfloat16(v1);
        ctxh[base0 + i] = h0;
        ctxl[base0 + i] = __float2bfloat16(v0 - __bfloat162float(h0));
        ctxh[base1 + i] = h1;
        ctxl[base1 + i] = __float2bfloat16(v1 - __bfloat162float(h1));
    }
}

// ---------------------------------------------------------------------------
// Launch. Inputs: X, ln_w, ln_b, W_in, W_out. Output fp32.
// ---------------------------------------------------------------------------
extern "C" void kernel_launch(void* const* d_in, const int* in_sizes, int n_in,
                              void* d_out, int out_size)
{
    const float* X     = (const float*)d_in[0];
    const float* ln_w  = (const float*)d_in[1];
    const float* ln_b  = (const float*)d_in[2];
    const float* W_in  = (const float*)d_in[3];
    const float* W_out = (const float*)d_in[4];
    float*       out   = (float*)d_out;

    float *pQKV;
    __nv_bfloat16 *pAhi, *pAlo, *pWhi, *pWlo, *pWoHi, *pWoLo, *pCh, *pCl;
    cudaGetSymbolAddress((void**)&pQKV,  g_QKV);
    cudaGetSymbolAddress((void**)&pAhi,  g_Ahi);
    cudaGetSymbolAddress((void**)&pAlo,  g_Alo);
    cudaGetSymbolAddress((void**)&pWhi,  g_Whi);
    cudaGetSymbolAddress((void**)&pWlo,  g_Wlo);
    cudaGetSymbolAddress((void**)&pWoHi, g_WoHi);
    cudaGetSymbolAddress((void**)&pWoLo, g_WoLo);
    cudaGetSymbolAddress((void**)&pCh,   g_CtxHi);
    cudaGetSymbolAddress((void**)&pCl,   g_CtxLo);

    // 0) Weight transpose + bf16 split
    wsplit_kernel<<<dim3(NQKV / 32, DD / 32), 256>>>(W_in,  pWhi,  pWlo,  NQKV);
    wsplit_kernel<<<dim3(DD   / 32, DD / 32), 256>>>(W_out, pWoHi, pWoLo, DD);

    // 1) LayerNorm -> bf16 hi/lo
    ln_kernel<<<MM, 256>>>(X, ln_w, ln_b, pAhi, pAlo);

    // 2) QKV projection (HMMA): [8192,2048] x [2048,6144]
    mma_gemm<0><<<dim3(NQKV / 128, MM / 128), 256>>>(
        pAhi, pAlo, pWhi, pWlo, nullptr, pQKV, NQKV);

    // 3) RoPE
    {
        const int total = MM * 2 * HH * 32;
        rope_kernel<<<(total + 255) / 256, 256>>>(pQKV);
    }

    // 4) Attention -> ctx bf16 hi/lo
    attn_kernel<<<dim3(SS / AQ, HH, BB), 256>>>(pQKV, pCh, pCl);

    // 5) Output projection + residual (HMMA)
    mma_gemm<1><<<dim3(DD / 128, MM / 128), 256>>>(
        pCh, pCl, pWoHi, pWoLo, X, out, DD);
}

// round 9
// speedup vs baseline: 7.0468x; 5.3964x over previous
#include <cuda_runtime.h>
#include <cuda_bf16.h>
#include <math.h>
#include <stdint.h>

// Problem constants (B=4, S=2048, D=2048, H=16, Dh=128)
#define BB    4
#define SS    2048
#define DD    2048
#define HH    16
#define DH    128
#define MM    (BB * SS)        // 8192 rows
#define NQKV  (3 * DD)         // 6144
#define GK    2048             // GEMM inner K

// ---------------------------------------------------------------------------
// Scratch: __device__ globals (allocation-guard-safe)
// ---------------------------------------------------------------------------
__device__ float          g_QKV[(size_t)MM * NQKV];    // 192 MB fp32 Q|K|V
__device__ __nv_bfloat16  g_Xnb[(size_t)MM * DD];      // LN out bf16
__device__ __nv_bfloat16  g_Wt [(size_t)NQKV * DD];    // W_in^T  [6144][2048]
__device__ __nv_bfloat16  g_WoT[(size_t)DD * DD];      // W_out^T [2048][2048]
__device__ __nv_bfloat16  g_Qb [(size_t)BB * HH * SS * DH];  // Q roped+scaled [b][h][s][d]
__device__ __nv_bfloat16  g_Kb [(size_t)BB * HH * SS * DH];  // K roped       [b][h][s][d]
__device__ __nv_bfloat16  g_Vt [(size_t)BB * HH * DH * SS];  // V transposed  [b][h][d][s]
__device__ __nv_bfloat16  g_ctx[(size_t)MM * DD];      // attention ctx [row][d]

// ---------------------------------------------------------------------------
// mma.sync m16n8k16 bf16 -> fp32
// ---------------------------------------------------------------------------
#define MMA16816(c, a, b_) \
    asm volatile("mma.sync.aligned.m16n8k16.row.col.f32.bf16.bf16.f32 " \
        "{%0,%1,%2,%3}, {%4,%5,%6,%7}, {%8,%9}, {%0,%1,%2,%3};" \
        : "+f"((c)[0]), "+f"((c)[1]), "+f"((c)[2]), "+f"((c)[3]) \
        : "r"((a)[0]), "r"((a)[1]), "r"((a)[2]), "r"((a)[3]), \
          "r"((b_)[0]), "r"((b_)[1]))

// pack two f32 -> bf16x2 (lo = first arg)
__device__ __forceinline__ uint32_t pack_bf16x2(float lo, float hi) {
    uint32_t r;
    asm("cvt.rn.bf16x2.f32 %0, %1, %2;" : "=r"(r) : "f"(hi), "f"(lo));
    return r;
}

// fast 2^y for y <= 0 (poly deg-5, rel err ~8e-5), FFMA-pipe only
__device__ __forceinline__ float exp2_fast(float y) {
    y = fmaxf(y, -60.f);
    float fl = floorf(y);
    float f  = y - fl;
    float p  = fmaf(f, 0.0013333558f, 0.0096181291f);
    p = fmaf(f, p, 0.0555041087f);
    p = fmaf(f, p, 0.2402265069f);
    p = fmaf(f, p, 0.6931471806f);
    p = fmaf(f, p, 1.0f);
    return __int_as_float(__float_as_int(p) + (((int)fl) << 23));
}

// ---------------------------------------------------------------------------
// Kernel 1: LayerNorm -> bf16
// ---------------------------------------------------------------------------
__global__ void __launch_bounds__(256) ln_kernel(
    const float* __restrict__ X, const float* __restrict__ w,
    const float* __restrict__ b, __nv_bfloat16* __restrict__ Xn)
{
    const int row = blockIdx.x;
    const int t   = threadIdx.x;
    const float4* xr = (const float4*)(X + (size_t)row * DD);

    float4 v0 = xr[t];
    float4 v1 = xr[t + 256];

    float s  = v0.x + v0.y + v0.z + v0.w + v1.x + v1.y + v1.z + v1.w;
    float sq = v0.x*v0.x + v0.y*v0.y + v0.z*v0.z + v0.w*v0.w
             + v1.x*v1.x + v1.y*v1.y + v1.z*v1.z + v1.w*v1.w;

    #pragma unroll
    for (int off = 16; off > 0; off >>= 1) {
        s  += __shfl_xor_sync(0xffffffffu, s,  off);
        sq += __shfl_xor_sync(0xffffffffu, sq, off);
    }
    __shared__ float sm[8], sm2[8];
    const int warp = t >> 5, lane = t & 31;
    if (lane == 0) { sm[warp] = s; sm2[warp] = sq; }
    __syncthreads();
    float S = 0.f, SQ = 0.f;
    #pragma unroll
    for (int i = 0; i < 8; i++) { S += sm[i]; SQ += sm2[i]; }

    const float mu  = S * (1.f / (float)DD);
    const float var = SQ * (1.f / (float)DD) - mu * mu;
    const float inv = rsqrtf(var + 1e-5f);

    const float4* wv = (const float4*)w;
    const float4* bv = (const float4*)b;
    float4 w0 = wv[t], w1 = wv[t + 256];
    float4 b0 = bv[t], b1 = bv[t + 256];

    __nv_bfloat16* H = Xn + (size_t)row * DD;
    H[t*4+0] = __float2bfloat16((v0.x - mu) * inv * w0.x + b0.x);
    H[t*4+1] = __float2bfloat16((v0.y - mu) * inv * w0.y + b0.y);
    H[t*4+2] = __float2bfloat16((v0.z - mu) * inv * w0.z + b0.z);
    H[t*4+3] = __float2bfloat16((v0.w - mu) * inv * w0.w + b0.w);
    H[(t+256)*4+0] = __float2bfloat16((v1.x - mu) * inv * w1.x + b1.x);
    H[(t+256)*4+1] = __float2bfloat16((v1.y - mu) * inv * w1.y + b1.y);
    H[(t+256)*4+2] = __float2bfloat16((v1.z - mu) * inv * w1.z + b1.z);
    H[(t+256)*4+3] = __float2bfloat16((v1.w - mu) * inv * w1.w + b1.w);
}

// ---------------------------------------------------------------------------
// Kernel 2: weight transpose -> bf16.  W[2048][Ncols] fp32 -> Wt[Ncols][2048]
// ---------------------------------------------------------------------------
__global__ void __launch_bounds__(256) wsplit_kernel(
    const float* __restrict__ W, __nv_bfloat16* __restrict__ Wt, int Ncols)
{
    __shared__ float ts[32][33];
    const int tx = threadIdx.x & 31, ty = threadIdx.x >> 5;   // 32x8
    const int n0 = blockIdx.x * 32, k0 = blockIdx.y * 32;

    #pragma unroll
    for (int j = 0; j < 4; j++) {
        int r = ty + j * 8;
        ts[r][tx] = W[(size_t)(k0 + r) * Ncols + n0 + tx];
    }
    __syncthreads();
    #pragma unroll
    for (int j = 0; j < 4; j++) {
        int r = ty + j * 8;
        Wt[(size_t)(n0 + r) * GK + k0 + tx] = __float2bfloat16(ts[tx][r]);
    }
}

// ---------------------------------------------------------------------------
// Kernel 3: bf16 GEMM on mma.sync.  C[M,N] = A @ B^T (+R).
// A=[M][2048] bf16, B=[N][2048] bf16 K-major.
// Tile 128x128, BK=32, 8 warps x (64x32), double-buffered smem.
// ---------------------------------------------------------------------------
#define BK    32
#define ASTR  40
#define NCH   64                       // 2048 / 32

template<int ADD>
__global__ void __launch_bounds__(256, 2) mma_gemm(
    const __nv_bfloat16* __restrict__ A, const __nv_bfloat16* __restrict__ B,
    const float* __restrict__ R, float* __restrict__ C, int N)
{
    __shared__ __nv_bfloat16 As[2][128 * ASTR];
    __shared__ __nv_bfloat16 Bs[2][128 * ASTR];

    const int tid  = threadIdx.x;
    const int wid  = tid >> 5, lane = tid & 31;
    const int gid  = lane >> 2, tid2 = lane & 3;
    const int wm   = wid & 1;
    const int wn   = wid >> 1;
    const int bm   = blockIdx.y * 128, bn = blockIdx.x * 128;

    float acc[4][4][4];
    #pragma unroll
    for (int i = 0; i < 4; i++)
        #pragma unroll
        for (int j = 0; j < 4; j++)
            #pragma unroll
            for (int q = 0; q < 4; q++) acc[i][j][q] = 0.f;

    const int r0 = tid >> 2;
    const int c8 = (tid & 3) * 8;

    *(uint4*)&As[0][ r0       * ASTR + c8] = *(const uint4*)(A + (size_t)(bm + r0     ) * GK + c8);
    *(uint4*)&As[0][(r0 + 64) * ASTR + c8] = *(const uint4*)(A + (size_t)(bm + r0 + 64) * GK + c8);
    *(uint4*)&Bs[0][ r0       * ASTR + c8] = *(const uint4*)(B + (size_t)(bn + r0     ) * GK + c8);
    *(uint4*)&Bs[0][(r0 + 64) * ASTR + c8] = *(const uint4*)(B + (size_t)(bn + r0 + 64) * GK + c8);
    __syncthreads();

    for (int kc = 0; kc < NCH; kc++) {
        const int cur = kc & 1;

        uint4 ra0, ra1, rb0, rb1;
        if (kc + 1 < NCH) {
            const int koff = (kc + 1) * BK;
            ra0 = *(const uint4*)(A + (size_t)(bm + r0     ) * GK + koff + c8);
            ra1 = *(const uint4*)(A + (size_t)(bm + r0 + 64) * GK + koff + c8);
            rb0 = *(const uint4*)(B + (size_t)(bn + r0     ) * GK + koff + c8);
            rb1 = *(const uint4*)(B + (size_t)(bn + r0 + 64) * GK + koff + c8);
        }

        const __nv_bfloat16* Ab = &As[cur][(wm * 64 + gid) * ASTR + tid2 * 2];
        const __nv_bfloat16* Bb = &Bs[cur][(wn * 32 + gid) * ASTR + tid2 * 2];
        #pragma unroll
        for (int ks = 0; ks < BK; ks += 16) {
            uint32_t af[4][4], bf_[4][2];
            #pragma unroll
            for (int mf = 0; mf < 4; mf++) {
                const __nv_bfloat16* p = Ab + mf * 16 * ASTR + ks;
                af[mf][0] = *(const uint32_t*)(p);
                af[mf][1] = *(const uint32_t*)(p + 8 * ASTR);
                af[mf][2] = *(const uint32_t*)(p + 8);
                af[mf][3] = *(const uint32_t*)(p + 8 * ASTR + 8);
            }
            #pragma unroll
            for (int nf = 0; nf < 4; nf++) {
                const __nv_bfloat16* p = Bb + nf * 8 * ASTR + ks;
                bf_[nf][0] = *(const uint32_t*)(p);
                bf_[nf][1] = *(const uint32_t*)(p + 8);
            }
            #pragma unroll
            for (int mf = 0; mf < 4; mf++)
                #pragma unroll
                for (int nf = 0; nf < 4; nf++)
                    MMA16816(acc[mf][nf], af[mf], bf_[nf]);
        }

        if (kc + 1 < NCH) {
            const int nxt = (kc + 1) & 1;
            *(uint4*)&As[nxt][ r0       * ASTR + c8] = ra0;
            *(uint4*)&As[nxt][(r0 + 64) * ASTR + c8] = ra1;
            *(uint4*)&Bs[nxt][ r0       * ASTR + c8] = rb0;
            *(uint4*)&Bs[nxt][(r0 + 64) * ASTR + c8] = rb1;
        }
        __syncthreads();
    }

    #pragma unroll
    for (int mf = 0; mf < 4; mf++) {
        #pragma unroll
        for (int nf = 0; nf < 4; nf++) {
            const int row = bm + wm * 64 + mf * 16 + gid;
            const int col = bn + wn * 32 + nf * 8 + tid2 * 2;
            size_t o0 = (size_t)row * N + col;
            size_t o1 = (size_t)(row + 8) * N + col;
            float2 v0 = make_float2(acc[mf][nf][0], acc[mf][nf][1]);
            float2 v1 = make_float2(acc[mf][nf][2], acc[mf][nf][3]);
            if (ADD) {
                float2 q0 = *(const float2*)(R + o0);
                float2 q1 = *(const float2*)(R + o1);
                v0.x += q0.x; v0.y += q0.y;
                v1.x += q1.x; v1.y += q1.y;
            }
            *(float2*)(C + o0) = v0;
            *(float2*)(C + o1) = v1;
        }
    }
}

// ---------------------------------------------------------------------------
// Kernel 4: RoPE + convert Q,K to bf16 [b][h][s][d].
// Q additionally scaled by log2(e)/sqrt(Dh) (log2-domain softmax).
// ---------------------------------------------------------------------------
__global__ void __launch_bounds__(256) ropeq_kernel(
    const float* __restrict__ QKV,
    __nv_bfloat16* __restrict__ Qb, __nv_bfloat16* __restrict__ Kb)
{
    const int idx = blockIdx.x * blockDim.x + threadIdx.x;
    const int total = MM * 2 * HH * 64;
    if (idx >= total) return;

    const int p    = idx & 63;
    const int head = (idx >> 6) & 15;
    const int sec  = (idx >> 10) & 1;         // 0 = Q, 1 = K
    const int row  = idx >> 11;
    const int s    = row & (SS - 1);
    const int b    = row >> 11;

    const size_t src = (size_t)row * NQKV + sec * DD + head * DH + p * 2;
    float x1 = QKV[src];
    float x2 = QKV[src + 1];

    if (p < 32) {
        const float inv = expf(-9.210340371976184f * ((float)p * (1.f / 32.f)));
        const float ang = (float)s * inv;
        float sn, cs;
        sincosf(ang, &sn, &cs);
        float r1 = x1 * cs - x2 * sn;
        float r2 = x2 * cs + x1 * sn;
        x1 = r1; x2 = r2;
    }

    const float qs = 0.08838834764831845f * 1.4426950408889634f;
    if (sec == 0) { x1 *= qs; x2 *= qs; }

    const size_t dst = (((size_t)b * HH + head) * SS + s) * DH + p * 2;
    __nv_bfloat16* out = (sec == 0) ? Qb : Kb;
    out[dst]     = __float2bfloat16(x1);
    out[dst + 1] = __float2bfloat16(x2);
}

// ---------------------------------------------------------------------------
// Kernel 5: V -> bf16 transposed [b][h][d][s]
// ---------------------------------------------------------------------------
__global__ void __launch_bounds__(256) vconv_kernel(
    const float* __restrict__ QKV, __nv_bfloat16* __restrict__ Vt)
{
    __shared__ float ts[32][33];
    const int tx = threadIdx.x & 31, ty = threadIdx.x >> 5;   // 32x8
    const int s0  = blockIdx.x * 32;
    const int hd0 = blockIdx.y * 32;          // h*128 + d0
    const int b   = blockIdx.z;

    #pragma unroll
    for (int j = 0; j < 4; j++) {
        int r = ty + j * 8;   // s offset
        ts[r][tx] = QKV[(size_t)(b * SS + s0 + r) * NQKV + 2 * DD + hd0 + tx];
    }
    __syncthreads();
    #pragma unroll
    for (int j = 0; j < 4; j++) {
        int dt = ty + j * 8;  // d offset
        Vt[((size_t)b * HH * DH + hd0 + dt) * SS + s0 + tx] =
            __float2bfloat16(ts[tx][dt]);
    }
}

// ---------------------------------------------------------------------------
// Kernel 6: flash attention on mma.sync.
// Block: 64 q-rows x head x batch; 4 warps, each warp 16 q-rows.
// Q fragments register-resident; K[64][136] and Vt[128][72] smem tiles.
// Softmax in log2 domain with FFMA-poly exp2. P acc->a-frag in-register.
// ---------------------------------------------------------------------------
#define AST 136
#define VST 72

__global__ void __launch_bounds__(128, 2) attn_mma(
    const __nv_bfloat16* __restrict__ Qb, const __nv_bfloat16* __restrict__ Kb,
    const __nv_bfloat16* __restrict__ Vt, __nv_bfloat16* __restrict__ ctx)
{
    __shared__ __nv_bfloat16 Ks[64 * AST];    // 17408 B
    __shared__ __nv_bfloat16 Vs[128 * VST];   // 18432 B

    const int tid = threadIdx.x, w = tid >> 5, lane = tid & 31;
    const int gid = lane >> 2, tid2 = lane & 3;
    const int qt = blockIdx.x, h = blockIdx.y, b = blockIdx.z;
    const int bh = b * HH + h;

    // Q fragments: 8 k-frags x 4 regs, rows w*16+gid / +8
    uint32_t qf[8][4];
    {
        const __nv_bfloat16* qp =
            Qb + ((size_t)bh * SS + qt * 64 + w * 16) * DH;
        #pragma unroll
        for (int kf = 0; kf < 8; kf++) {
            const __nv_bfloat16* p = qp + kf * 16 + tid2 * 2;
            qf[kf][0] = *(const uint32_t*)(p + (size_t)gid * DH);
            qf[kf][1] = *(const uint32_t*)(p + (size_t)(gid + 8) * DH);
            qf[kf][2] = *(const uint32_t*)(p + (size_t)gid * DH + 8);
            qf[kf][3] = *(const uint32_t*)(p + (size_t)(gid + 8) * DH + 8);
        }
    }

    float o[16][4];
    #pragma unroll
    for (int i = 0; i < 16; i++)
        #pragma unroll
        for (int q = 0; q < 4; q++) o[i][q] = 0.f;
    float m0 = -1e30f, m1 = -1e30f, l0 = 0.f, l1 = 0.f;

    const __nv_bfloat16* kgp = Kb + (size_t)bh * SS * DH;
    const __nv_bfloat16* vgp = Vt + (size_t)bh * DH * SS;

    for (int kt = 0; kt < SS / 64; kt++) {
        __syncthreads();
        // load K tile [64][128] and V tile [128][64]
        #pragma unroll
        for (int u = 0; u < 8; u++) {
            int f = tid + u * 128;
            int r = f >> 4, c = (f & 15) * 8;
            *(uint4*)&Ks[r * AST + c] =
                *(const uint4*)(kgp + (size_t)(kt * 64 + r) * DH + c);
        }
        #pragma unroll
        for (int u = 0; u < 8; u++) {
            int f = tid + u * 128;
            int d = f >> 3, c = (f & 7) * 8;
            *(uint4*)&Vs[d * VST + c] =
                *(const uint4*)(vgp + (size_t)d * SS + kt * 64 + c);
        }
        __syncthreads();

        // scores S[16 x 64] (log2 domain; scale folded into Q)
        float s[8][4];
        #pragma unroll
        for (int nf = 0; nf < 8; nf++)
            #pragma unroll
            for (int q = 0; q < 4; q++) s[nf][q] = 0.f;

        #pragma unroll
        for (int kf = 0; kf < 8; kf++) {
            #pragma unroll
            for (int nf = 0; nf < 8; nf++) {
                uint32_t bfr[2];
                const __nv_bfloat16* p =
                    &Ks[(nf * 8 + gid) * AST + kf * 16 + tid2 * 2];
                bfr[0] = *(const uint32_t*)(p);
                bfr[1] = *(const uint32_t*)(p + 8);
                MMA16816(s[nf], qf[kf], bfr);
            }
        }

        // online softmax (rows gid -> m0/l0, gid+8 -> m1/l1)
        float mx0 = -1e30f, mx1 = -1e30f;
        #pragma unroll
        for (int nf = 0; nf < 8; nf++) {
            mx0 = fmaxf(mx0, fmaxf(s[nf][0], s[nf][1]));
            mx1 = fmaxf(mx1, fmaxf(s[nf][2], s[nf][3]));
        }
        mx0 = fmaxf(mx0, __shfl_xor_sync(0xffffffffu, mx0, 1));
        mx0 = fmaxf(mx0, __shfl_xor_sync(0xffffffffu, mx0, 2));
        mx1 = fmaxf(mx1, __shfl_xor_sync(0xffffffffu, mx1, 1));
        mx1 = fmaxf(mx1, __shfl_xor_sync(0xffffffffu, mx1, 2));

        float nm0 = fmaxf(m0, mx0), nm1 = fmaxf(m1, mx1);
        float f0 = exp2_fast(m0 - nm0), f1 = exp2_fast(m1 - nm1);
        m0 = nm0; m1 = nm1;

        float sum0 = 0.f, sum1 = 0.f;
        #pragma unroll
        for (int nf = 0; nf < 8; nf++) {
            s[nf][0] = exp2_fast(s[nf][0] - m0);
            s[nf][1] = exp2_fast(s[nf][1] - m0);
            s[nf][2] = exp2_fast(s[nf][2] - m1);
            s[nf][3] = exp2_fast(s[nf][3] - m1);
            sum0 += s[nf][0] + s[nf][1];
            sum1 += s[nf][2] + s[nf][3];
        }
        sum0 += __shfl_xor_sync(0xffffffffu, sum0, 1);
        sum0 += __shfl_xor_sync(0xffffffffu, sum0, 2);
        sum1 += __shfl_xor_sync(0xffffffffu, sum1, 1);
        sum1 += __shfl_xor_sync(0xffffffffu, sum1, 2);
        l0 = l0 * f0 + sum0;
        l1 = l1 * f1 + sum1;

        #pragma unroll
        for (int nd = 0; nd < 16; nd++) {
            o[nd][0] *= f0; o[nd][1] *= f0;
            o[nd][2] *= f1; o[nd][3] *= f1;
        }

        // P @ V : P acc -> a-frags in-register, Vt b-frags from smem
        #pragma unroll
        for (int kf2 = 0; kf2 < 4; kf2++) {
            uint32_t pa[4];
            pa[0] = pack_bf16x2(s[2*kf2][0],   s[2*kf2][1]);
            pa[1] = pack_bf16x2(s[2*kf2][2],   s[2*kf2][3]);
            pa[2] = pack_bf16x2(s[2*kf2+1][0], s[2*kf2+1][1]);
            pa[3] = pack_bf16x2(s[2*kf2+1][2], s[2*kf2+1][3]);
            #pragma unroll
            for (int nd = 0; nd < 16; nd++) {
                uint32_t bfr[2];
                const __nv_bfloat16* p =
                    &Vs[(nd * 8 + gid) * VST + kf2 * 16 + tid2 * 2];
                bfr[0] = *(const uint32_t*)(p);
                bfr[1] = *(const uint32_t*)(p + 8);
                MMA16816(o[nd], pa, bfr);
            }
        }
    }

    // epilogue: normalize, write ctx [row][h*128+d] bf16
    const float il0 = 1.f / l0, il1 = 1.f / l1;
    const size_t row0 = (size_t)(b * SS + qt * 64 + w * 16 + gid);
    __nv_bfloat16* cp0 = ctx + row0 * DD + h * DH + tid2 * 2;
    __nv_bfloat16* cp1 = cp0 + 8 * DD;
    #pragma unroll
    for (int nd = 0; nd < 16; nd++) {
        *(uint32_t*)(cp0 + nd * 8) = pack_bf16x2(o[nd][0] * il0, o[nd][1] * il0);
        *(uint32_t*)(cp1 + nd * 8) = pack_bf16x2(o[nd][2] * il1, o[nd][3] * il1);
    }
}

// ---------------------------------------------------------------------------
// Launch. Inputs: X, ln_w, ln_b, W_in, W_out. Output fp32.
// ---------------------------------------------------------------------------
extern "C" void kernel_launch(void* const* d_in, const int* in_sizes, int n_in,
                              void* d_out, int out_size)
{
    const float* X     = (const float*)d_in[0];
    const float* ln_w  = (const float*)d_in[1];
    const float* ln_b  = (const float*)d_in[2];
    const float* W_in  = (const float*)d_in[3];
    const float* W_out = (const float*)d_in[4];
    float*       out   = (float*)d_out;

    float* pQKV;
    __nv_bfloat16 *pXn, *pWt, *pWoT, *pQb, *pKb, *pVt, *pCtx;
    cudaGetSymbolAddress((void**)&pQKV, g_QKV);
    cudaGetSymbolAddress((void**)&pXn,  g_Xnb);
    cudaGetSymbolAddress((void**)&pWt,  g_Wt);
    cudaGetSymbolAddress((void**)&pWoT, g_WoT);
    cudaGetSymbolAddress((void**)&pQb,  g_Qb);
    cudaGetSymbolAddress((void**)&pKb,  g_Kb);
    cudaGetSymbolAddress((void**)&pVt,  g_Vt);
    cudaGetSymbolAddress((void**)&pCtx, g_ctx);

    // 0) Weight transpose -> bf16
    wsplit_kernel<<<dim3(NQKV / 32, DD / 32), 256>>>(W_in,  pWt,  NQKV);
    wsplit_kernel<<<dim3(DD   / 32, DD / 32), 256>>>(W_out, pWoT, DD);

    // 1) LayerNorm -> bf16
    ln_kernel<<<MM, 256>>>(X, ln_w, ln_b, pXn);

    // 2) QKV projection (HMMA)
    mma_gemm<0><<<dim3(NQKV / 128, MM / 128), 256>>>(
        pXn, pWt, nullptr, pQKV, NQKV);

    // 3) RoPE + Q/K bf16 conversion
    {
        const int total = MM * 2 * HH * 64;
        ropeq_kernel<<<(total + 255) / 256, 256>>>(pQKV, pQb, pKb);
    }

    // 4) V transpose -> bf16
    vconv_kernel<<<dim3(SS / 32, HH * DH / 32, BB), 256>>>(pQKV, pVt);

    // 5) Attention (tensor-core flash)
    attn_mma<<<dim3(SS / 64, HH, BB), 128>>>(pQb, pKb, pVt, pCtx);

    // 6) Output projection + residual (HMMA)
    mma_gemm<1><<<dim3(DD / 128, MM / 128), 256>>>(
        pCtx, pWoT, X, out, DD);
}

// round 10
// speedup vs baseline: 8.3607x; 1.1864x over previous
#include <cuda_runtime.h>
#include <cuda_bf16.h>
#include <math.h>
#include <stdint.h>

// Problem constants (B=4, S=2048, D=2048, H=16, Dh=128)
#define BB    4
#define SS    2048
#define DD    2048
#define HH    16
#define DH    128
#define MM    (BB * SS)        // 8192 rows
#define NQKV  (3 * DD)         // 6144
#define GK    2048             // GEMM inner K

// ---------------------------------------------------------------------------
// Scratch: __device__ globals (allocation-guard-safe)
// ---------------------------------------------------------------------------
__device__ float          g_QKV[(size_t)MM * NQKV];    // 192 MB fp32 Q|K|V
__device__ __nv_bfloat16  g_Xnb[(size_t)MM * DD];      // LN out bf16
__device__ __nv_bfloat16  g_Wt [(size_t)NQKV * DD];    // W_in^T  [6144][2048]
__device__ __nv_bfloat16  g_WoT[(size_t)DD * DD];      // W_out^T [2048][2048]
__device__ __nv_bfloat16  g_Qb [(size_t)BB * HH * SS * DH];  // Q roped+scaled [b][h][s][d]
__device__ __nv_bfloat16  g_Kb [(size_t)BB * HH * SS * DH];  // K roped       [b][h][s][d]
__device__ __nv_bfloat16  g_Vt [(size_t)BB * HH * DH * SS];  // V transposed  [b][h][d][s]
__device__ __nv_bfloat16  g_ctx[(size_t)MM * DD];      // attention ctx [row][d]

// ---------------------------------------------------------------------------
// PTX helpers (all base-ISA: sm_80+ features, legal on plain sm_103)
// ---------------------------------------------------------------------------
#define MMA16816(c, a, b_) \
    asm volatile("mma.sync.aligned.m16n8k16.row.col.f32.bf16.bf16.f32 " \
        "{%0,%1,%2,%3}, {%4,%5,%6,%7}, {%8,%9}, {%0,%1,%2,%3};" \
        : "+f"((c)[0]), "+f"((c)[1]), "+f"((c)[2]), "+f"((c)[3]) \
        : "r"((a)[0]), "r"((a)[1]), "r"((a)[2]), "r"((a)[3]), \
          "r"((b_)[0]), "r"((b_)[1]))

#define LDSM4(r, addr) \
    asm volatile("ldmatrix.sync.aligned.m8n8.x4.shared.b16 {%0,%1,%2,%3}, [%4];" \
        : "=r"((r)[0]), "=r"((r)[1]), "=r"((r)[2]), "=r"((r)[3]) : "r"(addr))

#define CP_ASYNC16(dst, src) \
    asm volatile("cp.async.cg.shared.global [%0], [%1], 16;" :: "r"(dst), "l"(src))
#define CP_COMMIT()  asm volatile("cp.async.commit_group;")
#define CP_WAIT0()   asm volatile("cp.async.wait_group 0;")

__device__ __forceinline__ uint32_t pack_bf16x2(float lo, float hi) {
    uint32_t r;
    asm("cvt.rn.bf16x2.f32 %0, %1, %2;" : "=r"(r) : "f"(hi), "f"(lo));
    return r;
}

// fast 2^y for y <= 0 (poly deg-5, rel err ~8e-5), FFMA-pipe only
__device__ __forceinline__ float exp2_fast(float y) {
    y = fmaxf(y, -60.f);
    float fl = floorf(y);
    float f  = y - fl;
    float p  = fmaf(f, 0.0013333558f, 0.0096181291f);
    p = fmaf(f, p, 0.0555041087f);
    p = fmaf(f, p, 0.2402265069f);
    p = fmaf(f, p, 0.6931471806f);
    p = fmaf(f, p, 1.0f);
    return __int_as_float(__float_as_int(p) + (((int)fl) << 23));
}

// ---------------------------------------------------------------------------
// Kernel 1: LayerNorm -> bf16
// ---------------------------------------------------------------------------
__global__ void __launch_bounds__(256) ln_kernel(
    const float* __restrict__ X, const float* __restrict__ w,
    const float* __restrict__ b, __nv_bfloat16* __restrict__ Xn)
{
    const int row = blockIdx.x;
    const int t   = threadIdx.x;
    const float4* xr = (const float4*)(X + (size_t)row * DD);

    float4 v0 = xr[t];
    float4 v1 = xr[t + 256];

    float s  = v0.x + v0.y + v0.z + v0.w + v1.x + v1.y + v1.z + v1.w;
    float sq = v0.x*v0.x + v0.y*v0.y + v0.z*v0.z + v0.w*v0.w
             + v1.x*v1.x + v1.y*v1.y + v1.z*v1.z + v1.w*v1.w;

    #pragma unroll
    for (int off = 16; off > 0; off >>= 1) {
        s  += __shfl_xor_sync(0xffffffffu, s,  off);
        sq += __shfl_xor_sync(0xffffffffu, sq, off);
    }
    __shared__ float sm[8], sm2[8];
    const int warp = t >> 5, lane = t & 31;
    if (lane == 0) { sm[warp] = s; sm2[warp] = sq; }
    __syncthreads();
    float S = 0.f, SQ = 0.f;
    #pragma unroll
    for (int i = 0; i < 8; i++) { S += sm[i]; SQ += sm2[i]; }

    const float mu  = S * (1.f / (float)DD);
    const float var = SQ * (1.f / (float)DD) - mu * mu;
    const float inv = rsqrtf(var + 1e-5f);

    const float4* wv = (const float4*)w;
    const float4* bv = (const float4*)b;
    float4 w0 = wv[t], w1 = wv[t + 256];
    float4 b0 = bv[t], b1 = bv[t + 256];

    __nv_bfloat16* H = Xn + (size_t)row * DD;
    H[t*4+0] = __float2bfloat16((v0.x - mu) * inv * w0.x + b0.x);
    H[t*4+1] = __float2bfloat16((v0.y - mu) * inv * w0.y + b0.y);
    H[t*4+2] = __float2bfloat16((v0.z - mu) * inv * w0.z + b0.z);
    H[t*4+3] = __float2bfloat16((v0.w - mu) * inv * w0.w + b0.w);
    H[(t+256)*4+0] = __float2bfloat16((v1.x - mu) * inv * w1.x + b1.x);
    H[(t+256)*4+1] = __float2bfloat16((v1.y - mu) * inv * w1.y + b1.y);
    H[(t+256)*4+2] = __float2bfloat16((v1.z - mu) * inv * w1.z + b1.z);
    H[(t+256)*4+3] = __float2bfloat16((v1.w - mu) * inv * w1.w + b1.w);
}

// ---------------------------------------------------------------------------
// Kernel 2: weight transpose -> bf16.  W[2048][Ncols] fp32 -> Wt[Ncols][2048]
// ---------------------------------------------------------------------------
__global__ void __launch_bounds__(256) wsplit_kernel(
    const float* __restrict__ W, __nv_bfloat16* __restrict__ Wt, int Ncols)
{
    __shared__ float ts[32][33];
    const int tx = threadIdx.x & 31, ty = threadIdx.x >> 5;   // 32x8
    const int n0 = blockIdx.x * 32, k0 = blockIdx.y * 32;

    #pragma unroll
    for (int j = 0; j < 4; j++) {
        int r = ty + j * 8;
        ts[r][tx] = W[(size_t)(k0 + r) * Ncols + n0 + tx];
    }
    __syncthreads();
    #pragma unroll
    for (int j = 0; j < 4; j++) {
        int r = ty + j * 8;
        Wt[(size_t)(n0 + r) * GK + k0 + tx] = __float2bfloat16(ts[tx][r]);
    }
}

// ---------------------------------------------------------------------------
// Kernel 3: bf16 GEMM on mma.sync + ldmatrix + cp.async.
// C[M,N] = A @ B^T (+R). A=[M][2048] bf16, B=[N][2048] bf16 K-major.
// Tile 128x128, BK=32, 4 warps x (64x64 warp tile), cp.async double buffer.
// Per-chunk LDS reads: 32KB (was 48KB with 8x 64x32 warps).
// ---------------------------------------------------------------------------
#define BK    32
#define ASTR  40                       // row stride in bf16 (80B = 5x16B, odd -> conflict-free ldmatrix)
#define NCH   64                       // 2048 / 32

template<int ADD>
__global__ void __launch_bounds__(128, 2) mma_gemm(
    const __nv_bfloat16* __restrict__ A, const __nv_bfloat16* __restrict__ B,
    const float* __restrict__ R, float* __restrict__ C, int N)
{
    __shared__ __nv_bfloat16 As[2][128 * ASTR];   // 10240 B each buf
    __shared__ __nv_bfloat16 Bs[2][128 * ASTR];

    const int tid  = threadIdx.x;
    const int wid  = tid >> 5, lane = tid & 31;
    const int gid  = lane >> 2, tid2 = lane & 3;
    const int wm   = wid & 1;            // 2 m-warps  (64 rows)
    const int wn   = wid >> 1;           // 2 n-warps  (64 cols)
    const int bm   = blockIdx.y * 128, bn = blockIdx.x * 128;

    float acc[4][8][4];
    #pragma unroll
    for (int i = 0; i < 4; i++)
        #pragma unroll
        for (int j = 0; j < 8; j++)
            #pragma unroll
            for (int q = 0; q < 4; q++) acc[i][j][q] = 0.f;

    // gmem->smem: 128 threads x 4 uint4 per tile (A and B each)
    const int lr = tid >> 2;             // row 0..31 step -> rows via +32*u? no: f=tid+u*128
    (void)lr;

    // ldmatrix source addresses (per-warp fragment base)
    //  A x4: lanes 0-7 rows +0 k+0 | 8-15 rows +8 k+0 | 16-23 rows +0 k+8 | 24-31 rows +8 k+8
    const int a_row = wm * 64 + ((lane >> 3) & 1) * 8 + (lane & 7);
    const int a_k   = (lane >> 4) * 8;
    //  B x4: lanes 0-7 rows +0 k+0 | 8-15 rows +0 k+8 | 16-23 rows +8 k+0 | 24-31 rows +8 k+8
    const int b_row = wn * 64 + ((lane >> 4) & 1) * 8 + (lane & 7);
    const int b_k   = ((lane >> 3) & 1) * 8;

    #define LOAD_TILES(buf, koff) do { \
        _Pragma("unroll") \
        for (int u = 0; u < 4; u++) { \
            int f = tid + u * 128; \
            int r = f >> 2, cb = (f & 3) * 8; \
            uint32_t da = (uint32_t)__cvta_generic_to_shared(&As[buf][r * ASTR + cb]); \
            CP_ASYNC16(da, A + (size_t)(bm + r) * GK + (koff) + cb); \
            uint32_t db = (uint32_t)__cvta_generic_to_shared(&Bs[buf][r * ASTR + cb]); \
            CP_ASYNC16(db, B + (size_t)(bn + r) * GK + (koff) + cb); \
        } \
        CP_COMMIT(); \
    } while (0)

    LOAD_TILES(0, 0);
    CP_WAIT0();
    __syncthreads();

    for (int kc = 0; kc < NCH; kc++) {
        const int cur = kc & 1;

        if (kc + 1 < NCH) LOAD_TILES((kc + 1) & 1, (kc + 1) * BK);

        #pragma unroll
        for (int ks = 0; ks < BK; ks += 16) {
            uint32_t af[4][4], bf_[8][2];
            #pragma unroll
            for (int mf = 0; mf < 4; mf++) {
                uint32_t addr = (uint32_t)__cvta_generic_to_shared(
                    &As[cur][(a_row + mf * 16) * ASTR + ks + a_k]);
                LDSM4(af[mf], addr);
            }
            #pragma unroll
            for (int np = 0; np < 4; np++) {
                uint32_t r4[4];
                uint32_t addr = (uint32_t)__cvta_generic_to_shared(
                    &Bs[cur][(b_row + np * 16) * ASTR + ks + b_k]);
                LDSM4(r4, addr);
                bf_[2*np][0]   = r4[0]; bf_[2*np][1]   = r4[1];
                bf_[2*np+1][0] = r4[2]; bf_[2*np+1][1] = r4[3];
            }
            #pragma unroll
            for (int mf = 0; mf < 4; mf++)
                #pragma unroll
                for (int nf = 0; nf < 8; nf++)
                    MMA16816(acc[mf][nf], af[mf], bf_[nf]);
        }

        if (kc + 1 < NCH) CP_WAIT0();
        __syncthreads();
    }

    // epilogue: warp owns 64x64
    #pragma unroll
    for (int mf = 0; mf < 4; mf++) {
        #pragma unroll
        for (int nf = 0; nf < 8; nf++) {
            const int row = bm + wm * 64 + mf * 16 + gid;
            const int col = bn + wn * 64 + nf * 8 + tid2 * 2;
            size_t o0 = (size_t)row * N + col;
            size_t o1 = (size_t)(row + 8) * N + col;
            float2 v0 = make_float2(acc[mf][nf][0], acc[mf][nf][1]);
            float2 v1 = make_float2(acc[mf][nf][2], acc[mf][nf][3]);
            if (ADD) {
                float2 q0 = *(const float2*)(R + o0);
                float2 q1 = *(const float2*)(R + o1);
                v0.x += q0.x; v0.y += q0.y;
                v1.x += q1.x; v1.y += q1.y;
            }
            *(float2*)(C + o0) = v0;
            *(float2*)(C + o1) = v1;
        }
    }
    #undef LOAD_TILES
}

// ---------------------------------------------------------------------------
// Kernel 4: RoPE + convert Q,K to bf16 [b][h][s][d].
// Q additionally scaled by log2(e)/sqrt(Dh) (log2-domain softmax).
// ---------------------------------------------------------------------------
__global__ void __launch_bounds__(256) ropeq_kernel(
    const float* __restrict__ QKV,
    __nv_bfloat16* __restrict__ Qb, __nv_bfloat16* __restrict__ Kb)
{
    const int idx = blockIdx.x * blockDim.x + threadIdx.x;
    const int total = MM * 2 * HH * 64;
    if (idx >= total) return;

    const int p    = idx & 63;
    const int head = (idx >> 6) & 15;
    const int sec  = (idx >> 10) & 1;         // 0 = Q, 1 = K
    const int row  = idx >> 11;
    const int s    = row & (SS - 1);
    const int b    = row >> 11;

    const size_t src = (size_t)row * NQKV + sec * DD + head * DH + p * 2;
    float x1 = QKV[src];
    float x2 = QKV[src + 1];

    if (p < 32) {
        const float inv = expf(-9.210340371976184f * ((float)p * (1.f / 32.f)));
        const float ang = (float)s * inv;
        float sn, cs;
        sincosf(ang, &sn, &cs);
        float r1 = x1 * cs - x2 * sn;
        float r2 = x2 * cs + x1 * sn;
        x1 = r1; x2 = r2;
    }

    const float qs = 0.08838834764831845f * 1.4426950408889634f;
    if (sec == 0) { x1 *= qs; x2 *= qs; }

    const size_t dst = (((size_t)b * HH + head) * SS + s) * DH + p * 2;
    __nv_bfloat16* out = (sec == 0) ? Qb : Kb;
    out[dst]     = __float2bfloat16(x1);
    out[dst + 1] = __float2bfloat16(x2);
}

// ---------------------------------------------------------------------------
// Kernel 5: V -> bf16 transposed [b][h][d][s]
// ---------------------------------------------------------------------------
__global__ void __launch_bounds__(256) vconv_kernel(
    const float* __restrict__ QKV, __nv_bfloat16* __restrict__ Vt)
{
    __shared__ float ts[32][33];
    const int tx = threadIdx.x & 31, ty = threadIdx.x >> 5;   // 32x8
    const int s0  = blockIdx.x * 32;
    const int hd0 = blockIdx.y * 32;          // h*128 + d0
    const int b   = blockIdx.z;

    #pragma unroll
    for (int j = 0; j < 4; j++) {
        int r = ty + j * 8;   // s offset
        ts[r][tx] = QKV[(size_t)(b * SS + s0 + r) * NQKV + 2 * DD + hd0 + tx];
    }
    __syncthreads();
    #pragma unroll
    for (int j = 0; j < 4; j++) {
        int dt = ty + j * 8;  // d offset
        Vt[((size_t)b * HH * DH + hd0 + dt) * SS + s0 + tx] =
            __float2bfloat16(ts[tx][dt]);
    }
}

// ---------------------------------------------------------------------------
// Kernel 6: flash attention on mma.sync (unchanged from R8).
// ---------------------------------------------------------------------------
#define AST 136
#define VST 72

__global__ void __launch_bounds__(128, 2) attn_mma(
    const __nv_bfloat16* __restrict__ Qb, const __nv_bfloat16* __restrict__ Kb,
    const __nv_bfloat16* __restrict__ Vt, __nv_bfloat16* __restrict__ ctx)
{
    __shared__ __nv_bfloat16 Ks[64 * AST];    // 17408 B
    __shared__ __nv_bfloat16 Vs[128 * VST];   // 18432 B

    const int tid = threadIdx.x, w = tid >> 5, lane = tid & 31;
    const int gid = lane >> 2, tid2 = lane & 3;
    const int qt = blockIdx.x, h = blockIdx.y, b = blockIdx.z;
    const int bh = b * HH + h;

    uint32_t qf[8][4];
    {
        const __nv_bfloat16* qp =
            Qb + ((size_t)bh * SS + qt * 64 + w * 16) * DH;
        #pragma unroll
        for (int kf = 0; kf < 8; kf++) {
            const __nv_bfloat16* p = qp + kf * 16 + tid2 * 2;
            qf[kf][0] = *(const uint32_t*)(p + (size_t)gid * DH);
            qf[kf][1] = *(const uint32_t*)(p + (size_t)(gid + 8) * DH);
            qf[kf][2] = *(const uint32_t*)(p + (size_t)gid * DH + 8);
            qf[kf][3] = *(const uint32_t*)(p + (size_t)(gid + 8) * DH + 8);
        }
    }

    float o[16][4];
    #pragma unroll
    for (int i = 0; i < 16; i++)
        #pragma unroll
        for (int q = 0; q < 4; q++) o[i][q] = 0.f;
    float m0 = -1e30f, m1 = -1e30f, l0 = 0.f, l1 = 0.f;

    const __nv_bfloat16* kgp = Kb + (size_t)bh * SS * DH;
    const __nv_bfloat16* vgp = Vt + (size_t)bh * DH * SS;

    for (int kt = 0; kt < SS / 64; kt++) {
        __syncthreads();
        #pragma unroll
        for (int u = 0; u < 8; u++) {
            int f = tid + u * 128;
            int r = f >> 4, c = (f & 15) * 8;
            *(uint4*)&Ks[r * AST + c] =
                *(const uint4*)(kgp + (size_t)(kt * 64 + r) * DH + c);
        }
        #pragma unroll
        for (int u = 0; u < 8; u++) {
            int f = tid + u * 128;
            int d = f >> 3, c = (f & 7) * 8;
            *(uint4*)&Vs[d * VST + c] =
                *(const uint4*)(vgp + (size_t)d * SS + kt * 64 + c);
        }
        __syncthreads();

        float s[8][4];
        #pragma unroll
        for (int nf = 0; nf < 8; nf++)
            #pragma unroll
            for (int q = 0; q < 4; q++) s[nf][q] = 0.f;

        #pragma unroll
        for (int kf = 0; kf < 8; kf++) {
            #pragma unroll
            for (int nf = 0; nf < 8; nf++) {
                uint32_t bfr[2];
                const __nv_bfloat16* p =
                    &Ks[(nf * 8 + gid) * AST + kf * 16 + tid2 * 2];
                bfr[0] = *(const uint32_t*)(p);
                bfr[1] = *(const uint32_t*)(p + 8);
                MMA16816(s[nf], qf[kf], bfr);
            }
        }

        float mx0 = -1e30f, mx1 = -1e30f;
        #pragma unroll
        for (int nf = 0; nf < 8; nf++) {
            mx0 = fmaxf(mx0, fmaxf(s[nf][0], s[nf][1]));
            mx1 = fmaxf(mx1, fmaxf(s[nf][2], s[nf][3]));
        }
        mx0 = fmaxf(mx0, __shfl_xor_sync(0xffffffffu, mx0, 1));
        mx0 = fmaxf(mx0, __shfl_xor_sync(0xffffffffu, mx0, 2));
        mx1 = fmaxf(mx1, __shfl_xor_sync(0xffffffffu, mx1, 1));
        mx1 = fmaxf(mx1, __shfl_xor_sync(0xffffffffu, mx1, 2));

        float nm0 = fmaxf(m0, mx0), nm1 = fmaxf(m1, mx1);
        float f0 = exp2_fast(m0 - nm0), f1 = exp2_fast(m1 - nm1);
        m0 = nm0; m1 = nm1;

        float sum0 = 0.f, sum1 = 0.f;
        #pragma unroll
        for (int nf = 0; nf < 8; nf++) {
            s[nf][0] = exp2_fast(s[nf][0] - m0);
            s[nf][1] = exp2_fast(s[nf][1] - m0);
            s[nf][2] = exp2_fast(s[nf][2] - m1);
            s[nf][3] = exp2_fast(s[nf][3] - m1);
            sum0 += s[nf][0] + s[nf][1];
            sum1 += s[nf][2] + s[nf][3];
        }
        sum0 += __shfl_xor_sync(0xffffffffu, sum0, 1);
        sum0 += __shfl_xor_sync(0xffffffffu, sum0, 2);
        sum1 += __shfl_xor_sync(0xffffffffu, sum1, 1);
        sum1 += __shfl_xor_sync(0xffffffffu, sum1, 2);
        l0 = l0 * f0 + sum0;
        l1 = l1 * f1 + sum1;

        #pragma unroll
        for (int nd = 0; nd < 16; nd++) {
            o[nd][0] *= f0; o[nd][1] *= f0;
            o[nd][2] *= f1; o[nd][3] *= f1;
        }

        #pragma unroll
        for (int kf2 = 0; kf2 < 4; kf2++) {
            uint32_t pa[4];
            pa[0] = pack_bf16x2(s[2*kf2][0],   s[2*kf2][1]);
            pa[1] = pack_bf16x2(s[2*kf2][2],   s[2*kf2][3]);
            pa[2] = pack_bf16x2(s[2*kf2+1][0], s[2*kf2+1][1]);
            pa[3] = pack_bf16x2(s[2*kf2+1][2], s[2*kf2+1][3]);
            #pragma unroll
            for (int nd = 0; nd < 16; nd++) {
                uint32_t bfr[2];
                const __nv_bfloat16* p =
                    &Vs[(nd * 8 + gid) * VST + kf2 * 16 + tid2 * 2];
                bfr[0] = *(const uint32_t*)(p);
                bfr[1] = *(const uint32_t*)(p + 8);
                MMA16816(o[nd], pa, bfr);
            }
        }
    }

    const float il0 = 1.f / l0, il1 = 1.f / l1;
    const size_t row0 = (size_t)(b * SS + qt * 64 + w * 16 + gid);
    __nv_bfloat16* cp0 = ctx + row0 * DD + h * DH + tid2 * 2;
    __nv_bfloat16* cp1 = cp0 + 8 * DD;
    #pragma unroll
    for (int nd = 0; nd < 16; nd++) {
        *(uint32_t*)(cp0 + nd * 8) = pack_bf16x2(o[nd][0] * il0, o[nd][1] * il0);
        *(uint32_t*)(cp1 + nd * 8) = pack_bf16x2(o[nd][2] * il1, o[nd][3] * il1);
    }
}

// ---------------------------------------------------------------------------
// Launch. Inputs: X, ln_w, ln_b, W_in, W_out. Output fp32.
// ---------------------------------------------------------------------------
extern "C" void kernel_launch(void* const* d_in, const int* in_sizes, int n_in,
                              void* d_out, int out_size)
{
    const float* X     = (const float*)d_in[0];
    const float* ln_w  = (const float*)d_in[1];
    const float* ln_b  = (const float*)d_in[2];
    const float* W_in  = (const float*)d_in[3];
    const float* W_out = (const float*)d_in[4];
    float*       out   = (float*)d_out;

    float* pQKV;
    __nv_bfloat16 *pXn, *pWt, *pWoT, *pQb, *pKb, *pVt, *pCtx;
    cudaGetSymbolAddress((void**)&pQKV, g_QKV);
    cudaGetSymbolAddress((void**)&pXn,  g_Xnb);
    cudaGetSymbolAddress((void**)&pWt,  g_Wt);
    cudaGetSymbolAddress((void**)&pWoT, g_WoT);
    cudaGetSymbolAddress((void**)&pQb,  g_Qb);
    cudaGetSymbolAddress((void**)&pKb,  g_Kb);
    cudaGetSymbolAddress((void**)&pVt,  g_Vt);
    cudaGetSymbolAddress((void**)&pCtx, g_ctx);

    // 0) Weight transpose -> bf16
    wsplit_kernel<<<dim3(NQKV / 32, DD / 32), 256>>>(W_in,  pWt,  NQKV);
    wsplit_kernel<<<dim3(DD   / 32, DD / 32), 256>>>(W_out, pWoT, DD);

    // 1) LayerNorm -> bf16
    ln_kernel<<<MM, 256>>>(X, ln_w, ln_b, pXn);

    // 2) QKV projection (HMMA + ldmatrix + cp.async)
    mma_gemm<0><<<dim3(NQKV / 128, MM / 128), 128>>>(
        pXn, pWt, nullptr, pQKV, NQKV);

    // 3) RoPE + Q/K bf16 conversion
    {
        const int total = MM * 2 * HH * 64;
        ropeq_kernel<<<(total + 255) / 256, 256>>>(pQKV, pQb, pKb);
    }

    // 4) V transpose -> bf16
    vconv_kernel<<<dim3(SS / 32, HH * DH / 32, BB), 256>>>(pQKV, pVt);

    // 5) Attention (tensor-core flash)
    attn_mma<<<dim3(SS / 64, HH, BB), 128>>>(pQb, pKb, pVt, pCtx);

    // 6) Output projection + residual (HMMA)
    mma_gemm<1><<<dim3(DD / 128, MM / 128), 128>>>(
        pCtx, pWoT, X, out, DD);
}

// round 12
// speedup vs baseline: 8.7914x; 1.0515x over previous
#include <cuda_runtime.h>
#include <cuda_bf16.h>
#include <math.h>
#include <stdint.h>

// Problem constants (B=4, S=2048, D=2048, H=16, Dh=128)
#define BB    4
#define SS    2048
#define DD    2048
#define HH    16
#define DH    128
#define MM    (BB * SS)        // 8192 rows
#define NQKV  (3 * DD)         // 6144
#define GK    2048             // GEMM inner K

// ---------------------------------------------------------------------------
// Scratch: __device__ globals (allocation-guard-safe)
// ---------------------------------------------------------------------------
__device__ __nv_bfloat16  g_Xnb[(size_t)MM * DD];      // LN out bf16
__device__ __nv_bfloat16  g_Wt [(size_t)NQKV * DD];    // W_in^T  [6144][2048]
__device__ __nv_bfloat16  g_WoT[(size_t)DD * DD];      // W_out^T [2048][2048]
__device__ __nv_bfloat16  g_Qb [(size_t)BB * HH * SS * DH];  // Q roped+scaled [b][h][s][d]
__device__ __nv_bfloat16  g_Kb [(size_t)BB * HH * SS * DH];  // K roped       [b][h][s][d]
__device__ __nv_bfloat16  g_Vst[(size_t)MM * DD];      // V staging [row][h*Dh+d]
__device__ __nv_bfloat16  g_Vt [(size_t)BB * HH * DH * SS];  // V transposed [b][h][d][s]
__device__ __nv_bfloat16  g_ctx[(size_t)MM * DD];      // attention ctx [row][d]

// ---------------------------------------------------------------------------
// PTX helpers (base-ISA sm_80+, legal on plain sm_103)
// ---------------------------------------------------------------------------
#define MMA16816(c, a, b_) \
    asm volatile("mma.sync.aligned.m16n8k16.row.col.f32.bf16.bf16.f32 " \
        "{%0,%1,%2,%3}, {%4,%5,%6,%7}, {%8,%9}, {%0,%1,%2,%3};" \
        : "+f"((c)[0]), "+f"((c)[1]), "+f"((c)[2]), "+f"((c)[3]) \
        : "r"((a)[0]), "r"((a)[1]), "r"((a)[2]), "r"((a)[3]), \
          "r"((b_)[0]), "r"((b_)[1]))

#define LDSM4(r, addr) \
    asm volatile("ldmatrix.sync.aligned.m8n8.x4.shared.b16 {%0,%1,%2,%3}, [%4];" \
        : "=r"((r)[0]), "=r"((r)[1]), "=r"((r)[2]), "=r"((r)[3]) : "r"(addr))

#define CP_ASYNC16(dst, src) \
    asm volatile("cp.async.cg.shared.global [%0], [%1], 16;" :: "r"(dst), "l"(src))
#define CP_COMMIT()  asm volatile("cp.async.commit_group;")
#define CP_WAIT0()   asm volatile("cp.async.wait_group 0;")

__device__ __forceinline__ uint32_t pack_bf16x2(float lo, float hi) {
    uint32_t r;
    asm("cvt.rn.bf16x2.f32 %0, %1, %2;" : "=r"(r) : "f"(hi), "f"(lo));
    return r;
}

// fast 2^y for y <= 0 (poly deg-5, rel err ~8e-5), FFMA-pipe only
__device__ __forceinline__ float exp2_fast(float y) {
    y = fmaxf(y, -60.f);
    float fl = floorf(y);
    float f  = y - fl;
    float p  = fmaf(f, 0.0013333558f, 0.0096181291f);
    p = fmaf(f, p, 0.0555041087f);
    p = fmaf(f, p, 0.2402265069f);
    p = fmaf(f, p, 0.6931471806f);
    p = fmaf(f, p, 1.0f);
    return __int_as_float(__float_as_int(p) + (((int)fl) << 23));
}

// ---------------------------------------------------------------------------
// Kernel 1: LayerNorm -> bf16
// ---------------------------------------------------------------------------
__global__ void __launch_bounds__(256) ln_kernel(
    const float* __restrict__ X, const float* __restrict__ w,
    const float* __restrict__ b, __nv_bfloat16* __restrict__ Xn)
{
    const int row = blockIdx.x;
    const int t   = threadIdx.x;
    const float4* xr = (const float4*)(X + (size_t)row * DD);

    float4 v0 = xr[t];
    float4 v1 = xr[t + 256];

    float s  = v0.x + v0.y + v0.z + v0.w + v1.x + v1.y + v1.z + v1.w;
    float sq = v0.x*v0.x + v0.y*v0.y + v0.z*v0.z + v0.w*v0.w
             + v1.x*v1.x + v1.y*v1.y + v1.z*v1.z + v1.w*v1.w;

    #pragma unroll
    for (int off = 16; off > 0; off >>= 1) {
        s  += __shfl_xor_sync(0xffffffffu, s,  off);
        sq += __shfl_xor_sync(0xffffffffu, sq, off);
    }
    __shared__ float sm[8], sm2[8];
    const int warp = t >> 5, lane = t & 31;
    if (lane == 0) { sm[warp] = s; sm2[warp] = sq; }
    __syncthreads();
    float S = 0.f, SQ = 0.f;
    #pragma unroll
    for (int i = 0; i < 8; i++) { S += sm[i]; SQ += sm2[i]; }

    const float mu  = S * (1.f / (float)DD);
    const float var = SQ * (1.f / (float)DD) - mu * mu;
    const float inv = rsqrtf(var + 1e-5f);

    const float4* wv = (const float4*)w;
    const float4* bv = (const float4*)b;
    float4 w0 = wv[t], w1 = wv[t + 256];
    float4 b0 = bv[t], b1 = bv[t + 256];

    __nv_bfloat16* H = Xn + (size_t)row * DD;
    H[t*4+0] = __float2bfloat16((v0.x - mu) * inv * w0.x + b0.x);
    H[t*4+1] = __float2bfloat16((v0.y - mu) * inv * w0.y + b0.y);
    H[t*4+2] = __float2bfloat16((v0.z - mu) * inv * w0.z + b0.z);
    H[t*4+3] = __float2bfloat16((v0.w - mu) * inv * w0.w + b0.w);
    H[(t+256)*4+0] = __float2bfloat16((v1.x - mu) * inv * w1.x + b1.x);
    H[(t+256)*4+1] = __float2bfloat16((v1.y - mu) * inv * w1.y + b1.y);
    H[(t+256)*4+2] = __float2bfloat16((v1.z - mu) * inv * w1.z + b1.z);
    H[(t+256)*4+3] = __float2bfloat16((v1.w - mu) * inv * w1.w + b1.w);
}

// ---------------------------------------------------------------------------
// Kernel 2: weight transpose -> bf16.  W[2048][Ncols] fp32 -> Wt[Ncols][2048]
// ---------------------------------------------------------------------------
__global__ void __launch_bounds__(256) wsplit_kernel(
    const float* __restrict__ W, __nv_bfloat16* __restrict__ Wt, int Ncols)
{
    __shared__ float ts[32][33];
    const int tx = threadIdx.x & 31, ty = threadIdx.x >> 5;   // 32x8
    const int n0 = blockIdx.x * 32, k0 = blockIdx.y * 32;

    #pragma unroll
    for (int j = 0; j < 4; j++) {
        int r = ty + j * 8;
        ts[r][tx] = W[(size_t)(k0 + r) * Ncols + n0 + tx];
    }
    __syncthreads();
    #pragma unroll
    for (int j = 0; j < 4; j++) {
        int r = ty + j * 8;
        Wt[(size_t)(n0 + r) * GK + k0 + tx] = __float2bfloat16(ts[tx][r]);
    }
}

// ---------------------------------------------------------------------------
// GEMM core pieces (shared by both GEMM kernels)
// Tile 128x128, BK=32, 4 warps x (64x64 warp tile), cp.async double buffer.
// ---------------------------------------------------------------------------
#define BK    32
#define ASTR  40                       // 80B rows, odd x16B -> conflict-free ldmatrix
#define NCH   64                       // 2048 / 32

#define GEMM_PROLOG() \
    __shared__ __nv_bfloat16 As[2][128 * ASTR]; \
    __shared__ __nv_bfloat16 Bs[2][128 * ASTR]; \
    const int tid  = threadIdx.x; \
    const int wid  = tid >> 5, lane = tid & 31; \
    const int gid  = lane >> 2, tid2 = lane & 3; \
    const int wm   = wid & 1; \
    const int wn   = wid >> 1; \
    const int bm   = blockIdx.y * 128, bn = blockIdx.x * 128; \
    float acc[4][8][4]; \
    _Pragma("unroll") \
    for (int i = 0; i < 4; i++) \
        _Pragma("unroll") \
        for (int j = 0; j < 8; j++) \
            _Pragma("unroll") \
            for (int q = 0; q < 4; q++) acc[i][j][q] = 0.f; \
    const int a_row = wm * 64 + ((lane >> 3) & 1) * 8 + (lane & 7); \
    const int a_k   = (lane >> 4) * 8; \
    const int b_row = wn * 64 + ((lane >> 4) & 1) * 8 + (lane & 7); \
    const int b_k   = ((lane >> 3) & 1) * 8;

#define LOAD_TILES(buf, koff) do { \
    _Pragma("unroll") \
    for (int u = 0; u < 4; u++) { \
        int f = tid + u * 128; \
        int r = f >> 2, cb = (f & 3) * 8; \
        uint32_t da = (uint32_t)__cvta_generic_to_shared(&As[buf][r * ASTR + cb]); \
        CP_ASYNC16(da, A + (size_t)(bm + r) * GK + (koff) + cb); \
        uint32_t db = (uint32_t)__cvta_generic_to_shared(&Bs[buf][r * ASTR + cb]); \
        CP_ASYNC16(db, B + (size_t)(bn + r) * GK + (koff) + cb); \
    } \
    CP_COMMIT(); \
} while (0)

#define GEMM_MAINLOOP() \
    LOAD_TILES(0, 0); \
    CP_WAIT0(); \
    __syncthreads(); \
    for (int kc = 0; kc < NCH; kc++) { \
        const int cur = kc & 1; \
        if (kc + 1 < NCH) LOAD_TILES((kc + 1) & 1, (kc + 1) * BK); \
        _Pragma("unroll") \
        for (int ks = 0; ks < BK; ks += 16) { \
            uint32_t af[4][4], bf_[8][2]; \
            _Pragma("unroll") \
            for (int mf = 0; mf < 4; mf++) { \
                uint32_t addr = (uint32_t)__cvta_generic_to_shared( \
                    &As[cur][(a_row + mf * 16) * ASTR + ks + a_k]); \
                LDSM4(af[mf], addr); \
            } \
            _Pragma("unroll") \
            for (int np = 0; np < 4; np++) { \
                uint32_t r4[4]; \
                uint32_t addr = (uint32_t)__cvta_generic_to_shared( \
                    &Bs[cur][(b_row + np * 16) * ASTR + ks + b_k]); \
                LDSM4(r4, addr); \
                bf_[2*np][0]   = r4[0]; bf_[2*np][1]   = r4[1]; \
                bf_[2*np+1][0] = r4[2]; bf_[2*np+1][1] = r4[3]; \
            } \
            _Pragma("unroll") \
            for (int mf = 0; mf < 4; mf++) \
                _Pragma("unroll") \
                for (int nf = 0; nf < 8; nf++) \
                    MMA16816(acc[mf][nf], af[mf], bf_[nf]); \
        } \
        if (kc + 1 < NCH) CP_WAIT0(); \
        __syncthreads(); \
    }

// ---------------------------------------------------------------------------
// Kernel 3a: QKV GEMM with fused RoPE + bf16 conversion epilogue.
// C cols: [0,2048)=Q -> Qb (roped+scaled), [2048,4096)=K -> Kb (roped),
//         [4096,6144)=V -> Vst [row][h*Dh+d].
// Epilogue math on fp32 accumulators == old ropeq numerics exactly.
// ---------------------------------------------------------------------------
__global__ void __launch_bounds__(128, 2) mma_gemm_qkv(
    const __nv_bfloat16* __restrict__ A, const __nv_bfloat16* __restrict__ B,
    __nv_bfloat16* __restrict__ Qb, __nv_bfloat16* __restrict__ Kb,
    __nv_bfloat16* __restrict__ Vst)
{
    GEMM_PROLOG();
    GEMM_MAINLOOP();

    const float qs = 0.08838834764831845f * 1.4426950408889634f;

    #pragma unroll
    for (int nf = 0; nf < 8; nf++) {
        const int col  = bn + wn * 64 + nf * 8 + tid2 * 2;
        const int sec  = col >> 11;               // uniform per block
        const int rr   = col & 2047;
        const int head = rr >> 7;                 // uniform per block
        const int dcol = rr & 127;
        const bool rot = (dcol < 64);
        float invf = 0.f;
        if (rot)
            invf = expf(-9.210340371976184f * ((float)(dcol >> 1) * (1.f / 32.f)));

        #pragma unroll
        for (int mf = 0; mf < 4; mf++) {
            #pragma unroll
            for (int half = 0; half < 2; half++) {
                const int row = bm + wm * 64 + mf * 16 + gid + half * 8;
                const int s   = row & (SS - 1);
                const int b   = row >> 11;
                float x1 = acc[mf][nf][half * 2];
                float x2 = acc[mf][nf][half * 2 + 1];

                if (sec < 2) {
                    if (rot) {
                        float sn, cs;
                        sincosf((float)s * invf, &sn, &cs);
                        float r1 = x1 * cs - x2 * sn;
                        float r2 = x2 * cs + x1 * sn;
                        x1 = r1; x2 = r2;
                    }
                    if (sec == 0) { x1 *= qs; x2 *= qs; }
                    __nv_bfloat16* dst = (sec == 0) ? Qb : Kb;
                    *(uint32_t*)(dst + (((size_t)b * HH + head) * SS + s) * DH + dcol)
                        = pack_bf16x2(x1, x2);
                } else {
                    *(uint32_t*)(Vst + (size_t)row * DD + head * DH + dcol)
                        = pack_bf16x2(x1, x2);
                }
            }
        }
    }
}

// ---------------------------------------------------------------------------
// Kernel 3b: plain GEMM + residual (out projection), fp32 output.
// ---------------------------------------------------------------------------
__global__ void __launch_bounds__(128, 2) mma_gemm_out(
    const __nv_bfloat16* __restrict__ A, const __nv_bfloat16* __restrict__ B,
    const float* __restrict__ R, float* __restrict__ C, int N)
{
    GEMM_PROLOG();
    GEMM_MAINLOOP();

    #pragma unroll
    for (int mf = 0; mf < 4; mf++) {
        #pragma unroll
        for (int nf = 0; nf < 8; nf++) {
            const int row = bm + wm * 64 + mf * 16 + gid;
            const int col = bn + wn * 64 + nf * 8 + tid2 * 2;
            size_t o0 = (size_t)row * N + col;
            size_t o1 = (size_t)(row + 8) * N + col;
            float2 v0 = make_float2(acc[mf][nf][0], acc[mf][nf][1]);
            float2 v1 = make_float2(acc[mf][nf][2], acc[mf][nf][3]);
            float2 q0 = *(const float2*)(R + o0);
            float2 q1 = *(const float2*)(R + o1);
            v0.x += q0.x; v0.y += q0.y;
            v1.x += q1.x; v1.y += q1.y;
            *(float2*)(C + o0) = v0;
            *(float2*)(C + o1) = v1;
        }
    }
}

// ---------------------------------------------------------------------------
// Kernel 4: V staging bf16 -> bf16 transposed [b][h][d][s]
// ---------------------------------------------------------------------------
__global__ void __launch_bounds__(256) vconv_kernel(
    const __nv_bfloat16* __restrict__ Vst, __nv_bfloat16* __restrict__ Vt)
{
    __shared__ __nv_bfloat16 ts[32][33];
    const int tx = threadIdx.x & 31, ty = threadIdx.x >> 5;   // 32x8
    const int s0  = blockIdx.x * 32;
    const int hd0 = blockIdx.y * 32;          // h*128 + d0
    const int b   = blockIdx.z;

    #pragma unroll
    for (int j = 0; j < 4; j++) {
        int r = ty + j * 8;   // s offset
        ts[r][tx] = Vst[(size_t)(b * SS + s0 + r) * DD + hd0 + tx];
    }
    __syncthreads();
    #pragma unroll
    for (int j = 0; j < 4; j++) {
        int dt = ty + j * 8;  // d offset
        Vt[((size_t)b * HH * DH + hd0 + dt) * SS + s0 + tx] = ts[tx][dt];
    }
}

// ---------------------------------------------------------------------------
// Kernel 5: flash attention on mma.sync, cp.async double-buffered K/V.
// Dynamic smem: 2 x (64*AST + 128*VST) bf16 = 71680 B.
// ---------------------------------------------------------------------------
#define AST 136
#define VST 72
#define ATTN_SMEM (2 * (64 * AST + 128 * VST) * 2)

__global__ void __launch_bounds__(128, 2) attn_mma(
    const __nv_bfloat16* __restrict__ Qb, const __nv_bfloat16* __restrict__ Kb,
    const __nv_bfloat16* __restrict__ Vt, __nv_bfloat16* __restrict__ ctx)
{
    extern __shared__ __nv_bfloat16 dsm[];
    __nv_bfloat16* KsBase = dsm;                   // 2 x 64*AST
    __nv_bfloat16* VsBase = dsm + 2 * 64 * AST;    // 2 x 128*VST

    const int tid = threadIdx.x, w = tid >> 5, lane = tid & 31;
    const int gid = lane >> 2, tid2 = lane & 3;
    const int qt = blockIdx.x, h = blockIdx.y, b = blockIdx.z;
    const int bh = b * HH + h;

    const __nv_bfloat16* kgp = Kb + (size_t)bh * SS * DH;
    const __nv_bfloat16* vgp = Vt + (size_t)bh * DH * SS;

    #define ATTN_LOAD(buf, kt_) do { \
        __nv_bfloat16* Kd = KsBase + (buf) * 64 * AST; \
        __nv_bfloat16* Vd = VsBase + (buf) * 128 * VST; \
        _Pragma("unroll") \
        for (int u = 0; u < 8; u++) { \
            int f = tid + u * 128; \
            int r = f >> 4, c = (f & 15) * 8; \
            uint32_t d_ = (uint32_t)__cvta_generic_to_shared(&Kd[r * AST + c]); \
            CP_ASYNC16(d_, kgp + (size_t)((kt_) * 64 + r) * DH + c); \
        } \
        _Pragma("unroll") \
        for (int u = 0; u < 8; u++) { \
            int f = tid + u * 128; \
            int d2 = f >> 3, c = (f & 7) * 8; \
            uint32_t d_ = (uint32_t)__cvta_generic_to_shared(&Vd[d2 * VST + c]); \
            CP_ASYNC16(d_, vgp + (size_t)d2 * SS + (kt_) * 64 + c); \
        } \
        CP_COMMIT(); \
    } while (0)

    // Q fragments: 8 k-frags x 4 regs, rows w*16+gid / +8
    uint32_t qf[8][4];
    {
        const __nv_bfloat16* qp =
            Qb + ((size_t)bh * SS + qt * 64 + w * 16) * DH;
        #pragma unroll
        for (int kf = 0; kf < 8; kf++) {
            const __nv_bfloat16* p = qp + kf * 16 + tid2 * 2;
            qf[kf][0] = *(const uint32_t*)(p + (size_t)gid * DH);
            qf[kf][1] = *(const uint32_t*)(p + (size_t)(gid + 8) * DH);
            qf[kf][2] = *(const uint32_t*)(p + (size_t)gid * DH + 8);
            qf[kf][3] = *(const uint32_t*)(p + (size_t)(gid + 8) * DH + 8);
        }
    }

    float o[16][4];
    #pragma unroll
    for (int i = 0; i < 16; i++)
        #pragma unroll
        for (int q = 0; q < 4; q++) o[i][q] = 0.f;
    float m0 = -1e30f, m1 = -1e30f, l0 = 0.f, l1 = 0.f;

    ATTN_LOAD(0, 0);
    CP_WAIT0();
    __syncthreads();

    for (int kt = 0; kt < SS / 64; kt++) {
        const int cur = kt & 1;
        if (kt + 1 < SS / 64) ATTN_LOAD((kt + 1) & 1, kt + 1);

        const __nv_bfloat16* Ks = KsBase + cur * 64 * AST;
        const __nv_bfloat16* Vs = VsBase + cur * 128 * VST;

        // scores S[16 x 64] (log2 domain; scale folded into Q)
        float s[8][4];
        #pragma unroll
        for (int nf = 0; nf < 8; nf++)
            #pragma unroll
            for (int q = 0; q < 4; q++) s[nf][q] = 0.f;

        #pragma unroll
        for (int kf = 0; kf < 8; kf++) {
            #pragma unroll
            for (int nf = 0; nf < 8; nf++) {
                uint32_t bfr[2];
                const __nv_bfloat16* p =
                    &Ks[(nf * 8 + gid) * AST + kf * 16 + tid2 * 2];
                bfr[0] = *(const uint32_t*)(p);
                bfr[1] = *(const uint32_t*)(p + 8);
                MMA16816(s[nf], qf[kf], bfr);
            }
        }

        // online softmax (rows gid -> m0/l0, gid+8 -> m1/l1)
        float mx0 = -1e30f, mx1 = -1e30f;
        #pragma unroll
        for (int nf = 0; nf < 8; nf++) {
            mx0 = fmaxf(mx0, fmaxf(s[nf][0], s[nf][1]));
            mx1 = fmaxf(mx1, fmaxf(s[nf][2], s[nf][3]));
        }
        mx0 = fmaxf(mx0, __shfl_xor_sync(0xffffffffu, mx0, 1));
        mx0 = fmaxf(mx0, __shfl_xor_sync(0xffffffffu, mx0, 2));
        mx1 = fmaxf(mx1, __shfl_xor_sync(0xffffffffu, mx1, 1));
        mx1 = fmaxf(mx1, __shfl_xor_sync(0xffffffffu, mx1, 2));

        float nm0 = fmaxf(m0, mx0), nm1 = fmaxf(m1, mx1);
        float f0 = exp2_fast(m0 - nm0), f1 = exp2_fast(m1 - nm1);
        m0 = nm0; m1 = nm1;

        float sum0 = 0.f, sum1 = 0.f;
        #pragma unroll
        for (int nf = 0; nf < 8; nf++) {
            s[nf][0] = exp2_fast(s[nf][0] - m0);
            s[nf][1] = exp2_fast(s[nf][1] - m0);
            s[nf][2] = exp2_fast(s[nf][2] - m1);
            s[nf][3] = exp2_fast(s[nf][3] - m1);
            sum0 += s[nf][0] + s[nf][1];
            sum1 += s[nf][2] + s[nf][3];
        }
        sum0 += __shfl_xor_sync(0xffffffffu, sum0, 1);
        sum0 += __shfl_xor_sync(0xffffffffu, sum0, 2);
        sum1 += __shfl_xor_sync(0xffffffffu, sum1, 1);
        sum1 += __shfl_xor_sync(0xffffffffu, sum1, 2);
        l0 = l0 * f0 + sum0;
        l1 = l1 * f1 + sum1;

        #pragma unroll
        for (int nd = 0; nd < 16; nd++) {
            o[nd][0] *= f0; o[nd][1] *= f0;
            o[nd][2] *= f1; o[nd][3] *= f1;
        }

        // P @ V : P acc -> a-frags in-register, Vt b-frags from smem
        #pragma unroll
        for (int kf2 = 0; kf2 < 4; kf2++) {
            uint32_t pa[4];
            pa[0] = pack_bf16x2(s[2*kf2][0],   s[2*kf2][1]);
            pa[1] = pack_bf16x2(s[2*kf2][2],   s[2*kf2][3]);
            pa[2] = pack_bf16x2(s[2*kf2+1][0], s[2*kf2+1][1]);
            pa[3] = pack_bf16x2(s[2*kf2+1][2], s[2*kf2+1][3]);
            #pragma unroll
            for (int nd = 0; nd < 16; nd++) {
                uint32_t bfr[2];
                const __nv_bfloat16* p =
                    &Vs[(nd * 8 + gid) * VST + kf2 * 16 + tid2 * 2];
                bfr[0] = *(const uint32_t*)(p);
                bfr[1] = *(const uint32_t*)(p + 8);
                MMA16816(o[nd], pa, bfr);
            }
        }

        if (kt + 1 < SS / 64) CP_WAIT0();
        __syncthreads();
    }

    // epilogue: normalize, write ctx [row][h*128+d] bf16
    const float il0 = 1.f / l0, il1 = 1.f / l1;
    const size_t row0 = (size_t)(b * SS + qt * 64 + w * 16 + gid);
    __nv_bfloat16* cp0 = ctx + row0 * DD + h * DH + tid2 * 2;
    __nv_bfloat16* cp1 = cp0 + 8 * DD;
    #pragma unroll
    for (int nd = 0; nd < 16; nd++) {
        *(uint32_t*)(cp0 + nd * 8) = pack_bf16x2(o[nd][0] * il0, o[nd][1] * il0);
        *(uint32_t*)(cp1 + nd * 8) = pack_bf16x2(o[nd][2] * il1, o[nd][3] * il1);
    }
    #undef ATTN_LOAD
}

// ---------------------------------------------------------------------------
// Launch. Inputs: X, ln_w, ln_b, W_in, W_out. Output fp32.
// ---------------------------------------------------------------------------
extern "C" void kernel_launch(void* const* d_in, const int* in_sizes, int n_in,
                              void* d_out, int out_size)
{
    const float* X     = (const float*)d_in[0];
    const float* ln_w  = (const float*)d_in[1];
    const float* ln_b  = (const float*)d_in[2];
    const float* W_in  = (const float*)d_in[3];
    const float* W_out = (const float*)d_in[4];
    float*       out   = (float*)d_out;

    __nv_bfloat16 *pXn, *pWt, *pWoT, *pQb, *pKb, *pVst, *pVt, *pCtx;
    cudaGetSymbolAddress((void**)&pXn,  g_Xnb);
    cudaGetSymbolAddress((void**)&pWt,  g_Wt);
    cudaGetSymbolAddress((void**)&pWoT, g_WoT);
    cudaGetSymbolAddress((void**)&pQb,  g_Qb);
    cudaGetSymbolAddress((void**)&pKb,  g_Kb);
    cudaGetSymbolAddress((void**)&pVst, g_Vst);
    cudaGetSymbolAddress((void**)&pVt,  g_Vt);
    cudaGetSymbolAddress((void**)&pCtx, g_ctx);

    cudaFuncSetAttribute(attn_mma,
        cudaFuncAttributeMaxDynamicSharedMemorySize, ATTN_SMEM);

    // 0) Weight transpose -> bf16
    wsplit_kernel<<<dim3(NQKV / 32, DD / 32), 256>>>(W_in,  pWt,  NQKV);
    wsplit_kernel<<<dim3(DD   / 32, DD / 32), 256>>>(W_out, pWoT, DD);

    // 1) LayerNorm -> bf16
    ln_kernel<<<MM, 256>>>(X, ln_w, ln_b, pXn);

    // 2) QKV projection with fused RoPE + bf16 conversion
    mma_gemm_qkv<<<dim3(NQKV / 128, MM / 128), 128>>>(
        pXn, pWt, pQb, pKb, pVst);

    // 3) V transpose bf16 -> [b][h][d][s]
    vconv_kernel<<<dim3(SS / 32, HH * DH / 32, BB), 256>>>(pVst, pVt);

    // 4) Attention (tensor-core flash, cp.async pipelined)
    attn_mma<<<dim3(SS / 64, HH, BB), 128, ATTN_SMEM>>>(pQb, pKb, pVt, pCtx);

    // 5) Output projection + residual
    mma_gemm_out<<<dim3(DD / 128, MM / 128), 128>>>(
        pCtx, pWoT, X, out, DD);
}

// round 13
// speedup vs baseline: 9.3157x; 1.0596x over previous
#include <cuda_runtime.h>
#include <cuda_bf16.h>
#include <math.h>
#include <stdint.h>

// Problem constants (B=4, S=2048, D=2048, H=16, Dh=128)
#define BB    4
#define SS    2048
#define DD    2048
#define HH    16
#define DH    128
#define MM    (BB * SS)        // 8192 rows
#define NQKV  (3 * DD)         // 6144
#define GK    2048             // GEMM inner K

// ---------------------------------------------------------------------------
// Scratch: __device__ globals (allocation-guard-safe)
// ---------------------------------------------------------------------------
__device__ __nv_bfloat16  g_Xnb[(size_t)MM * DD];      // LN out bf16
__device__ __nv_bfloat16  g_Wt [(size_t)NQKV * DD];    // W_in^T  [6144][2048]
__device__ __nv_bfloat16  g_WoT[(size_t)DD * DD];      // W_out^T [2048][2048]
__device__ __nv_bfloat16  g_Qb [(size_t)BB * HH * SS * DH];  // Q roped+scaled [b][h][s][d]
__device__ __nv_bfloat16  g_Kb [(size_t)BB * HH * SS * DH];  // K roped       [b][h][s][d]
__device__ __nv_bfloat16  g_Vst[(size_t)MM * DD];      // V staging [row][h*Dh+d]
__device__ __nv_bfloat16  g_Vt [(size_t)BB * HH * DH * SS];  // V transposed [b][h][d][s]
__device__ __nv_bfloat16  g_ctx[(size_t)MM * DD];      // attention ctx [row][d]

// ---------------------------------------------------------------------------
// PTX helpers (base-ISA sm_80+, legal on plain sm_103)
// ---------------------------------------------------------------------------
#define MMA16816(c, a, b_) \
    asm volatile("mma.sync.aligned.m16n8k16.row.col.f32.bf16.bf16.f32 " \
        "{%0,%1,%2,%3}, {%4,%5,%6,%7}, {%8,%9}, {%0,%1,%2,%3};" \
        : "+f"((c)[0]), "+f"((c)[1]), "+f"((c)[2]), "+f"((c)[3]) \
        : "r"((a)[0]), "r"((a)[1]), "r"((a)[2]), "r"((a)[3]), \
          "r"((b_)[0]), "r"((b_)[1]))

#define LDSM4(r, addr) \
    asm volatile("ldmatrix.sync.aligned.m8n8.x4.shared.b16 {%0,%1,%2,%3}, [%4];" \
        : "=r"((r)[0]), "=r"((r)[1]), "=r"((r)[2]), "=r"((r)[3]) : "r"(addr))

#define CP_ASYNC16(dst, src) \
    asm volatile("cp.async.cg.shared.global [%0], [%1], 16;" :: "r"(dst), "l"(src))
#define CP_COMMIT()  asm volatile("cp.async.commit_group;")
#define CP_WAIT0()   asm volatile("cp.async.wait_group 0;")

__device__ __forceinline__ uint32_t pack_bf16x2(float lo, float hi) {
    uint32_t r;
    asm("cvt.rn.bf16x2.f32 %0, %1, %2;" : "=r"(r) : "f"(hi), "f"(lo));
    return r;
}

// fast 2^y for y <= 0 (poly deg-5, rel err ~8e-5), FFMA-pipe only
__device__ __forceinline__ float exp2_fast(float y) {
    y = fmaxf(y, -60.f);
    float fl = floorf(y);
    float f  = y - fl;
    float p  = fmaf(f, 0.0013333558f, 0.0096181291f);
    p = fmaf(f, p, 0.0555041087f);
    p = fmaf(f, p, 0.2402265069f);
    p = fmaf(f, p, 0.6931471806f);
    p = fmaf(f, p, 1.0f);
    return __int_as_float(__float_as_int(p) + (((int)fl) << 23));
}

// ---------------------------------------------------------------------------
// Kernel 1: LayerNorm -> bf16
// ---------------------------------------------------------------------------
__global__ void __launch_bounds__(256) ln_kernel(
    const float* __restrict__ X, const float* __restrict__ w,
    const float* __restrict__ b, __nv_bfloat16* __restrict__ Xn)
{
    const int row = blockIdx.x;
    const int t   = threadIdx.x;
    const float4* xr = (const float4*)(X + (size_t)row * DD);

    float4 v0 = xr[t];
    float4 v1 = xr[t + 256];

    float s  = v0.x + v0.y + v0.z + v0.w + v1.x + v1.y + v1.z + v1.w;
    float sq = v0.x*v0.x + v0.y*v0.y + v0.z*v0.z + v0.w*v0.w
             + v1.x*v1.x + v1.y*v1.y + v1.z*v1.z + v1.w*v1.w;

    #pragma unroll
    for (int off = 16; off > 0; off >>= 1) {
        s  += __shfl_xor_sync(0xffffffffu, s,  off);
        sq += __shfl_xor_sync(0xffffffffu, sq, off);
    }
    __shared__ float sm[8], sm2[8];
    const int warp = t >> 5, lane = t & 31;
    if (lane == 0) { sm[warp] = s; sm2[warp] = sq; }
    __syncthreads();
    float S = 0.f, SQ = 0.f;
    #pragma unroll
    for (int i = 0; i < 8; i++) { S += sm[i]; SQ += sm2[i]; }

    const float mu  = S * (1.f / (float)DD);
    const float var = SQ * (1.f / (float)DD) - mu * mu;
    const float inv = rsqrtf(var + 1e-5f);

    const float4* wv = (const float4*)w;
    const float4* bv = (const float4*)b;
    float4 w0 = wv[t], w1 = wv[t + 256];
    float4 b0 = bv[t], b1 = bv[t + 256];

    __nv_bfloat16* H = Xn + (size_t)row * DD;
    H[t*4+0] = __float2bfloat16((v0.x - mu) * inv * w0.x + b0.x);
    H[t*4+1] = __float2bfloat16((v0.y - mu) * inv * w0.y + b0.y);
    H[t*4+2] = __float2bfloat16((v0.z - mu) * inv * w0.z + b0.z);
    H[t*4+3] = __float2bfloat16((v0.w - mu) * inv * w0.w + b0.w);
    H[(t+256)*4+0] = __float2bfloat16((v1.x - mu) * inv * w1.x + b1.x);
    H[(t+256)*4+1] = __float2bfloat16((v1.y - mu) * inv * w1.y + b1.y);
    H[(t+256)*4+2] = __float2bfloat16((v1.z - mu) * inv * w1.z + b1.z);
    H[(t+256)*4+3] = __float2bfloat16((v1.w - mu) * inv * w1.w + b1.w);
}

// ---------------------------------------------------------------------------
// Kernel 2: weight transpose -> bf16.  W[2048][Ncols] fp32 -> Wt[Ncols][2048]
// ---------------------------------------------------------------------------
__global__ void __launch_bounds__(256) wsplit_kernel(
    const float* __restrict__ W, __nv_bfloat16* __restrict__ Wt, int Ncols)
{
    __shared__ float ts[32][33];
    const int tx = threadIdx.x & 31, ty = threadIdx.x >> 5;   // 32x8
    const int n0 = blockIdx.x * 32, k0 = blockIdx.y * 32;

    #pragma unroll
    for (int j = 0; j < 4; j++) {
        int r = ty + j * 8;
        ts[r][tx] = W[(size_t)(k0 + r) * Ncols + n0 + tx];
    }
    __syncthreads();
    #pragma unroll
    for (int j = 0; j < 4; j++) {
        int r = ty + j * 8;
        Wt[(size_t)(n0 + r) * GK + k0 + tx] = __float2bfloat16(ts[tx][r]);
    }
}

// ---------------------------------------------------------------------------
// GEMM core pieces.  Tile 128x128, BK=32, 4 warps x (64x64), cp.async x2.
// ---------------------------------------------------------------------------
#define BK    32
#define ASTR  40                       // 80B rows, odd x16B -> conflict-free ldmatrix
#define NCH   64                       // 2048 / 32

#define GEMM_PROLOG() \
    __shared__ __nv_bfloat16 As[2][128 * ASTR]; \
    __shared__ __nv_bfloat16 Bs[2][128 * ASTR]; \
    const int tid  = threadIdx.x; \
    const int wid  = tid >> 5, lane = tid & 31; \
    const int gid  = lane >> 2, tid2 = lane & 3; \
    const int wm   = wid & 1; \
    const int wn   = wid >> 1; \
    const int bm   = blockIdx.y * 128, bn = blockIdx.x * 128; \
    float acc[4][8][4]; \
    _Pragma("unroll") \
    for (int i = 0; i < 4; i++) \
        _Pragma("unroll") \
        for (int j = 0; j < 8; j++) \
            _Pragma("unroll") \
            for (int q = 0; q < 4; q++) acc[i][j][q] = 0.f; \
    const int a_row = wm * 64 + ((lane >> 3) & 1) * 8 + (lane & 7); \
    const int a_k   = (lane >> 4) * 8; \
    const int b_row = wn * 64 + ((lane >> 4) & 1) * 8 + (lane & 7); \
    const int b_k   = ((lane >> 3) & 1) * 8;

#define LOAD_TILES(buf, koff) do { \
    _Pragma("unroll") \
    for (int u = 0; u < 4; u++) { \
        int f = tid + u * 128; \
        int r = f >> 2, cb = (f & 3) * 8; \
        uint32_t da = (uint32_t)__cvta_generic_to_shared(&As[buf][r * ASTR + cb]); \
        CP_ASYNC16(da, A + (size_t)(bm + r) * GK + (koff) + cb); \
        uint32_t db = (uint32_t)__cvta_generic_to_shared(&Bs[buf][r * ASTR + cb]); \
        CP_ASYNC16(db, B + (size_t)(bn + r) * GK + (koff) + cb); \
    } \
    CP_COMMIT(); \
} while (0)

#define GEMM_MAINLOOP() \
    LOAD_TILES(0, 0); \
    CP_WAIT0(); \
    __syncthreads(); \
    for (int kc = 0; kc < NCH; kc++) { \
        const int cur = kc & 1; \
        if (kc + 1 < NCH) LOAD_TILES((kc + 1) & 1, (kc + 1) * BK); \
        _Pragma("unroll") \
        for (int ks = 0; ks < BK; ks += 16) { \
            uint32_t af[4][4], bf_[8][2]; \
            _Pragma("unroll") \
            for (int mf = 0; mf < 4; mf++) { \
                uint32_t addr = (uint32_t)__cvta_generic_to_shared( \
                    &As[cur][(a_row + mf * 16) * ASTR + ks + a_k]); \
                LDSM4(af[mf], addr); \
            } \
            _Pragma("unroll") \
            for (int np = 0; np < 4; np++) { \
                uint32_t r4[4]; \
                uint32_t addr = (uint32_t)__cvta_generic_to_shared( \
                    &Bs[cur][(b_row + np * 16) * ASTR + ks + b_k]); \
                LDSM4(r4, addr); \
                bf_[2*np][0]   = r4[0]; bf_[2*np][1]   = r4[1]; \
                bf_[2*np+1][0] = r4[2]; bf_[2*np+1][1] = r4[3]; \
            } \
            _Pragma("unroll") \
            for (int mf = 0; mf < 4; mf++) \
                _Pragma("unroll") \
                for (int nf = 0; nf < 8; nf++) \
                    MMA16816(acc[mf][nf], af[mf], bf_[nf]); \
        } \
        if (kc + 1 < NCH) CP_WAIT0(); \
        __syncthreads(); \
    }

// ---------------------------------------------------------------------------
// Kernel 3a: QKV GEMM with fused RoPE + bf16 conversion epilogue (MUFU math).
// ---------------------------------------------------------------------------
__global__ void __launch_bounds__(128, 2) mma_gemm_qkv(
    const __nv_bfloat16* __restrict__ A, const __nv_bfloat16* __restrict__ B,
    __nv_bfloat16* __restrict__ Qb, __nv_bfloat16* __restrict__ Kb,
    __nv_bfloat16* __restrict__ Vst)
{
    GEMM_PROLOG();
    GEMM_MAINLOOP();

    const float qs = 0.08838834764831845f * 1.4426950408889634f;

    #pragma unroll
    for (int nf = 0; nf < 8; nf++) {
        const int col  = bn + wn * 64 + nf * 8 + tid2 * 2;
        const int sec  = col >> 11;               // uniform per block
        const int rr   = col & 2047;
        const int head = rr >> 7;                 // uniform per block
        const int dcol = rr & 127;
        const bool rot = (dcol < 64);
        float invf = 0.f;
        if (rot)
            invf = __expf(-9.210340371976184f * ((float)(dcol >> 1) * (1.f / 32.f)));

        #pragma unroll
        for (int mf = 0; mf < 4; mf++) {
            #pragma unroll
            for (int half = 0; half < 2; half++) {
                const int row = bm + wm * 64 + mf * 16 + gid + half * 8;
                const int s   = row & (SS - 1);
                const int b   = row >> 11;
                float x1 = acc[mf][nf][half * 2];
                float x2 = acc[mf][nf][half * 2 + 1];

                if (sec < 2) {
                    if (rot) {
                        float sn, cs;
                        __sincosf((float)s * invf, &sn, &cs);
                        float r1 = x1 * cs - x2 * sn;
                        float r2 = x2 * cs + x1 * sn;
                        x1 = r1; x2 = r2;
                    }
                    if (sec == 0) { x1 *= qs; x2 *= qs; }
                    __nv_bfloat16* dst = (sec == 0) ? Qb : Kb;
                    *(uint32_t*)(dst + (((size_t)b * HH + head) * SS + s) * DH + dcol)
                        = pack_bf16x2(x1, x2);
                } else {
                    *(uint32_t*)(Vst + (size_t)row * DD + head * DH + dcol)
                        = pack_bf16x2(x1, x2);
                }
            }
        }
    }
}

// ---------------------------------------------------------------------------
// Kernel 3b: plain GEMM + residual (out projection), fp32 output.
// ---------------------------------------------------------------------------
__global__ void __launch_bounds__(128, 2) mma_gemm_out(
    const __nv_bfloat16* __restrict__ A, const __nv_bfloat16* __restrict__ B,
    const float* __restrict__ R, float* __restrict__ C, int N)
{
    GEMM_PROLOG();
    GEMM_MAINLOOP();

    #pragma unroll
    for (int mf = 0; mf < 4; mf++) {
        #pragma unroll
        for (int nf = 0; nf < 8; nf++) {
            const int row = bm + wm * 64 + mf * 16 + gid;
            const int col = bn + wn * 64 + nf * 8 + tid2 * 2;
            size_t o0 = (size_t)row * N + col;
            size_t o1 = (size_t)(row + 8) * N + col;
            float2 v0 = make_float2(acc[mf][nf][0], acc[mf][nf][1]);
            float2 v1 = make_float2(acc[mf][nf][2], acc[mf][nf][3]);
            float2 q0 = *(const float2*)(R + o0);
            float2 q1 = *(const float2*)(R + o1);
            v0.x += q0.x; v0.y += q0.y;
            v1.x += q1.x; v1.y += q1.y;
            *(float2*)(C + o0) = v0;
            *(float2*)(C + o1) = v1;
        }
    }
}

// ---------------------------------------------------------------------------
// Kernel 4: V staging bf16 -> bf16 transposed [b][h][d][s]
// ---------------------------------------------------------------------------
__global__ void __launch_bounds__(256) vconv_kernel(
    const __nv_bfloat16* __restrict__ Vst, __nv_bfloat16* __restrict__ Vt)
{
    __shared__ __nv_bfloat16 ts[32][33];
    const int tx = threadIdx.x & 31, ty = threadIdx.x >> 5;   // 32x8
    const int s0  = blockIdx.x * 32;
    const int hd0 = blockIdx.y * 32;          // h*128 + d0
    const int b   = blockIdx.z;

    #pragma unroll
    for (int j = 0; j < 4; j++) {
        int r = ty + j * 8;   // s offset
        ts[r][tx] = Vst[(size_t)(b * SS + s0 + r) * DD + hd0 + tx];
    }
    __syncthreads();
    #pragma unroll
    for (int j = 0; j < 4; j++) {
        int dt = ty + j * 8;  // d offset
        Vt[((size_t)b * HH * DH + hd0 + dt) * SS + s0 + tx] = ts[tx][dt];
    }
}

// ---------------------------------------------------------------------------
// Kernel 5: flash attention on mma.sync; cp.async double buffer; ldmatrix
// for K and V b-fragments (same lane mapping as GEMM B path).
// ---------------------------------------------------------------------------
#define AST 136
#define VST 72
#define ATTN_SMEM (2 * (64 * AST + 128 * VST) * 2)

__global__ void __launch_bounds__(128, 2) attn_mma(
    const __nv_bfloat16* __restrict__ Qb, const __nv_bfloat16* __restrict__ Kb,
    const __nv_bfloat16* __restrict__ Vt, __nv_bfloat16* __restrict__ ctx)
{
    extern __shared__ __nv_bfloat16 dsm[];
    __nv_bfloat16* KsBase = dsm;                   // 2 x 64*AST
    __nv_bfloat16* VsBase = dsm + 2 * 64 * AST;    // 2 x 128*VST

    const int tid = threadIdx.x, w = tid >> 5, lane = tid & 31;
    const int gid = lane >> 2, tid2 = lane & 3;
    const int qt = blockIdx.x, h = blockIdx.y, b = blockIdx.z;
    const int bh = b * HH + h;

    // ldmatrix lane mapping for B operands (same as GEMM)
    const int bl_row = ((lane >> 4) & 1) * 8 + (lane & 7);
    const int bl_k   = ((lane >> 3) & 1) * 8;

    const __nv_bfloat16* kgp = Kb + (size_t)bh * SS * DH;
    const __nv_bfloat16* vgp = Vt + (size_t)bh * DH * SS;

    #define ATTN_LOAD(buf, kt_) do { \
        __nv_bfloat16* Kd = KsBase + (buf) * 64 * AST; \
        __nv_bfloat16* Vd = VsBase + (buf) * 128 * VST; \
        _Pragma("unroll") \
        for (int u = 0; u < 8; u++) { \
            int f = tid + u * 128; \
            int r = f >> 4, c = (f & 15) * 8; \
            uint32_t d_ = (uint32_t)__cvta_generic_to_shared(&Kd[r * AST + c]); \
            CP_ASYNC16(d_, kgp + (size_t)((kt_) * 64 + r) * DH + c); \
        } \
        _Pragma("unroll") \
        for (int u = 0; u < 8; u++) { \
            int f = tid + u * 128; \
            int d2 = f >> 3, c = (f & 7) * 8; \
            uint32_t d_ = (uint32_t)__cvta_generic_to_shared(&Vd[d2 * VST + c]); \
            CP_ASYNC16(d_, vgp + (size_t)d2 * SS + (kt_) * 64 + c); \
        } \
        CP_COMMIT(); \
    } while (0)

    // Q fragments: 8 k-frags x 4 regs
    uint32_t qf[8][4];
    {
        const __nv_bfloat16* qp =
            Qb + ((size_t)bh * SS + qt * 64 + w * 16) * DH;
        #pragma unroll
        for (int kf = 0; kf < 8; kf++) {
            const __nv_bfloat16* p = qp + kf * 16 + tid2 * 2;
            qf[kf][0] = *(const uint32_t*)(p + (size_t)gid * DH);
            qf[kf][1] = *(const uint32_t*)(p + (size_t)(gid + 8) * DH);
            qf[kf][2] = *(const uint32_t*)(p + (size_t)gid * DH + 8);
            qf[kf][3] = *(const uint32_t*)(p + (size_t)(gid + 8) * DH + 8);
        }
    }

    float o[16][4];
    #pragma unroll
    for (int i = 0; i < 16; i++)
        #pragma unroll
        for (int q = 0; q < 4; q++) o[i][q] = 0.f;
    float m0 = -1e30f, m1 = -1e30f, l0 = 0.f, l1 = 0.f;

    ATTN_LOAD(0, 0);
    CP_WAIT0();
    __syncthreads();

    for (int kt = 0; kt < SS / 64; kt++) {
        const int cur = kt & 1;
        if (kt + 1 < SS / 64) ATTN_LOAD((kt + 1) & 1, kt + 1);

        const __nv_bfloat16* Ks = KsBase + cur * 64 * AST;
        const __nv_bfloat16* Vs = VsBase + cur * 128 * VST;

        // scores S[16 x 64] via ldmatrix B-frags
        float s[8][4];
        #pragma unroll
        for (int nf = 0; nf < 8; nf++)
            #pragma unroll
            for (int q = 0; q < 4; q++) s[nf][q] = 0.f;

        #pragma unroll
        for (int kf = 0; kf < 8; kf++) {
            #pragma unroll
            for (int np = 0; np < 4; np++) {
                uint32_t r4[4];
                uint32_t addr = (uint32_t)__cvta_generic_to_shared(
                    (void*)&Ks[(np * 16 + bl_row) * AST + kf * 16 + bl_k]);
                LDSM4(r4, addr);
                MMA16816(s[2*np],     qf[kf], r4);
                MMA16816(s[2*np + 1], qf[kf], r4 + 2);
            }
        }

        // online softmax (rows gid -> m0/l0, gid+8 -> m1/l1)
        float mx0 = -1e30f, mx1 = -1e30f;
        #pragma unroll
        for (int nf = 0; nf < 8; nf++) {
            mx0 = fmaxf(mx0, fmaxf(s[nf][0], s[nf][1]));
            mx1 = fmaxf(mx1, fmaxf(s[nf][2], s[nf][3]));
        }
        mx0 = fmaxf(mx0, __shfl_xor_sync(0xffffffffu, mx0, 1));
        mx0 = fmaxf(mx0, __shfl_xor_sync(0xffffffffu, mx0, 2));
        mx1 = fmaxf(mx1, __shfl_xor_sync(0xffffffffu, mx1, 1));
        mx1 = fmaxf(mx1, __shfl_xor_sync(0xffffffffu, mx1, 2));

        float nm0 = fmaxf(m0, mx0), nm1 = fmaxf(m1, mx1);
        float f0 = exp2_fast(m0 - nm0), f1 = exp2_fast(m1 - nm1);
        m0 = nm0; m1 = nm1;

        float sum0 = 0.f, sum1 = 0.f;
        #pragma unroll
        for (int nf = 0; nf < 8; nf++) {
            s[nf][0] = exp2_fast(s[nf][0] - m0);
            s[nf][1] = exp2_fast(s[nf][1] - m0);
            s[nf][2] = exp2_fast(s[nf][2] - m1);
            s[nf][3] = exp2_fast(s[nf][3] - m1);
            sum0 += s[nf][0] + s[nf][1];
            sum1 += s[nf][2] + s[nf][3];
        }
        sum0 += __shfl_xor_sync(0xffffffffu, sum0, 1);
        sum0 += __shfl_xor_sync(0xffffffffu, sum0, 2);
        sum1 += __shfl_xor_sync(0xffffffffu, sum1, 1);
        sum1 += __shfl_xor_sync(0xffffffffu, sum1, 2);
        l0 = l0 * f0 + sum0;
        l1 = l1 * f1 + sum1;

        #pragma unroll
        for (int nd = 0; nd < 16; nd++) {
            o[nd][0] *= f0; o[nd][1] *= f0;
            o[nd][2] *= f1; o[nd][3] *= f1;
        }

        // P @ V via ldmatrix B-frags
        #pragma unroll
        for (int kf2 = 0; kf2 < 4; kf2++) {
            uint32_t pa[4];
            pa[0] = pack_bf16x2(s[2*kf2][0],   s[2*kf2][1]);
            pa[1] = pack_bf16x2(s[2*kf2][2],   s[2*kf2][3]);
            pa[2] = pack_bf16x2(s[2*kf2+1][0], s[2*kf2+1][1]);
            pa[3] = pack_bf16x2(s[2*kf2+1][2], s[2*kf2+1][3]);
            #pragma unroll
            for (int np2 = 0; np2 < 8; np2++) {
                uint32_t r4[4];
                uint32_t addr = (uint32_t)__cvta_generic_to_shared(
                    (void*)&Vs[(np2 * 16 + bl_row) * VST + kf2 * 16 + bl_k]);
                LDSM4(r4, addr);
                MMA16816(o[2*np2],     pa, r4);
                MMA16816(o[2*np2 + 1], pa, r4 + 2);
            }
        }

        if (kt + 1 < SS / 64) CP_WAIT0();
        __syncthreads();
    }

    // epilogue: normalize, write ctx [row][h*128+d] bf16
    const float il0 = 1.f / l0, il1 = 1.f / l1;
    const size_t row0 = (size_t)(b * SS + qt * 64 + w * 16 + gid);
    __nv_bfloat16* cp0 = ctx + row0 * DD + h * DH + tid2 * 2;
    __nv_bfloat16* cp1 = cp0 + 8 * DD;
    #pragma unroll
    for (int nd = 0; nd < 16; nd++) {
        *(uint32_t*)(cp0 + nd * 8) = pack_bf16x2(o[nd][0] * il0, o[nd][1] * il0);
        *(uint32_t*)(cp1 + nd * 8) = pack_bf16x2(o[nd][2] * il1, o[nd][3] * il1);
    }
    #undef ATTN_LOAD
}

// ---------------------------------------------------------------------------
// Launch. Inputs: X, ln_w, ln_b, W_in, W_out. Output fp32.
// ---------------------------------------------------------------------------
extern "C" void kernel_launch(void* const* d_in, const int* in_sizes, int n_in,
                              void* d_out, int out_size)
{
    const float* X     = (const float*)d_in[0];
    const float* ln_w  = (const float*)d_in[1];
    const float* ln_b  = (const float*)d_in[2];
    const float* W_in  = (const float*)d_in[3];
    const float* W_out = (const float*)d_in[4];
    float*       out   = (float*)d_out;

    __nv_bfloat16 *pXn, *pWt, *pWoT, *pQb, *pKb, *pVst, *pVt, *pCtx;
    cudaGetSymbolAddress((void**)&pXn,  g_Xnb);
    cudaGetSymbolAddress((void**)&pWt,  g_Wt);
    cudaGetSymbolAddress((void**)&pWoT, g_WoT);
    cudaGetSymbolAddress((void**)&pQb,  g_Qb);
    cudaGetSymbolAddress((void**)&pKb,  g_Kb);
    cudaGetSymbolAddress((void**)&pVst, g_Vst);
    cudaGetSymbolAddress((void**)&pVt,  g_Vt);
    cudaGetSymbolAddress((void**)&pCtx, g_ctx);

    cudaFuncSetAttribute(attn_mma,
        cudaFuncAttributeMaxDynamicSharedMemorySize, ATTN_SMEM);

    // 0) Weight transpose -> bf16
    wsplit_kernel<<<dim3(NQKV / 32, DD / 32), 256>>>(W_in,  pWt,  NQKV);
    wsplit_kernel<<<dim3(DD   / 32, DD / 32), 256>>>(W_out, pWoT, DD);

    // 1) LayerNorm -> bf16
    ln_kernel<<<MM, 256>>>(X, ln_w, ln_b, pXn);

    // 2) QKV projection with fused RoPE + bf16 conversion
    mma_gemm_qkv<<<dim3(NQKV / 128, MM / 128), 128>>>(
        pXn, pWt, pQb, pKb, pVst);

    // 3) V transpose bf16 -> [b][h][d][s]
    vconv_kernel<<<dim3(SS / 32, HH * DH / 32, BB), 256>>>(pVst, pVt);

    // 4) Attention (tensor-core flash, cp.async + ldmatrix)
    attn_mma<<<dim3(SS / 64, HH, BB), 128, ATTN_SMEM>>>(pQb, pKb, pVt, pCtx);

    // 5) Output projection + residual
    mma_gemm_out<<<dim3(DD / 128, MM / 128), 128>>>(
        pCtx, pWoT, X, out, DD);
}

// round 14
// speedup vs baseline: 9.4764x; 1.0173x over previous
#include <cuda_runtime.h>
#include <cuda_bf16.h>
#include <math.h>
#include <stdint.h>

// Problem constants (B=4, S=2048, D=2048, H=16, Dh=128)
#define BB    4
#define SS    2048
#define DD    2048
#define HH    16
#define DH    128
#define MM    (BB * SS)        // 8192 rows
#define NQKV  (3 * DD)         // 6144
#define GK    2048             // GEMM inner K

// ---------------------------------------------------------------------------
// Scratch: __device__ globals (allocation-guard-safe)
// ---------------------------------------------------------------------------
__device__ __nv_bfloat16  g_Xnb[(size_t)MM * DD];      // LN out bf16
__device__ __nv_bfloat16  g_Wt [(size_t)NQKV * DD];    // W_in^T  [6144][2048]
__device__ __nv_bfloat16  g_WoT[(size_t)DD * DD];      // W_out^T [2048][2048]
__device__ __nv_bfloat16  g_Qb [(size_t)BB * HH * SS * DH];  // Q roped+scaled [b][h][s][d]
__device__ __nv_bfloat16  g_Kb [(size_t)BB * HH * SS * DH];  // K roped       [b][h][s][d]
__device__ __nv_bfloat16  g_Vst[(size_t)MM * DD];      // V staging [row][h*Dh+d]
__device__ __nv_bfloat16  g_Vt [(size_t)BB * HH * DH * SS];  // V transposed [b][h][d][s]
__device__ __nv_bfloat16  g_ctx[(size_t)MM * DD];      // attention ctx [row][d]

// ---------------------------------------------------------------------------
// PTX helpers (base-ISA sm_80+, legal on plain sm_103)
// ---------------------------------------------------------------------------
#define MMA16816(c, a, b_) \
    asm volatile("mma.sync.aligned.m16n8k16.row.col.f32.bf16.bf16.f32 " \
        "{%0,%1,%2,%3}, {%4,%5,%6,%7}, {%8,%9}, {%0,%1,%2,%3};" \
        : "+f"((c)[0]), "+f"((c)[1]), "+f"((c)[2]), "+f"((c)[3]) \
        : "r"((a)[0]), "r"((a)[1]), "r"((a)[2]), "r"((a)[3]), \
          "r"((b_)[0]), "r"((b_)[1]))

#define LDSM4(r, addr) \
    asm volatile("ldmatrix.sync.aligned.m8n8.x4.shared.b16 {%0,%1,%2,%3}, [%4];" \
        : "=r"((r)[0]), "=r"((r)[1]), "=r"((r)[2]), "=r"((r)[3]) : "r"(addr))

#define CP_ASYNC16(dst, src) \
    asm volatile("cp.async.cg.shared.global [%0], [%1], 16;" :: "r"(dst), "l"(src))
#define CP_COMMIT()  asm volatile("cp.async.commit_group;")
#define CP_WAIT0()   asm volatile("cp.async.wait_group 0;")

__device__ __forceinline__ uint32_t pack_bf16x2(float lo, float hi) {
    uint32_t r;
    asm("cvt.rn.bf16x2.f32 %0, %1, %2;" : "=r"(r) : "f"(hi), "f"(lo));
    return r;
}

// fast 2^y for y <= 0 (poly deg-5, rel err ~8e-5), FFMA-pipe only
__device__ __forceinline__ float exp2_fast(float y) {
    y = fmaxf(y, -60.f);
    float fl = floorf(y);
    float f  = y - fl;
    float p  = fmaf(f, 0.0013333558f, 0.0096181291f);
    p = fmaf(f, p, 0.0555041087f);
    p = fmaf(f, p, 0.2402265069f);
    p = fmaf(f, p, 0.6931471806f);
    p = fmaf(f, p, 1.0f);
    return __int_as_float(__float_as_int(p) + (((int)fl) << 23));
}

// ---------------------------------------------------------------------------
// Kernel 1: LayerNorm -> bf16
// ---------------------------------------------------------------------------
__global__ void __launch_bounds__(256) ln_kernel(
    const float* __restrict__ X, const float* __restrict__ w,
    const float* __restrict__ b, __nv_bfloat16* __restrict__ Xn)
{
    const int row = blockIdx.x;
    const int t   = threadIdx.x;
    const float4* xr = (const float4*)(X + (size_t)row * DD);

    float4 v0 = xr[t];
    float4 v1 = xr[t + 256];

    float s  = v0.x + v0.y + v0.z + v0.w + v1.x + v1.y + v1.z + v1.w;
    float sq = v0.x*v0.x + v0.y*v0.y + v0.z*v0.z + v0.w*v0.w
             + v1.x*v1.x + v1.y*v1.y + v1.z*v1.z + v1.w*v1.w;

    #pragma unroll
    for (int off = 16; off > 0; off >>= 1) {
        s  += __shfl_xor_sync(0xffffffffu, s,  off);
        sq += __shfl_xor_sync(0xffffffffu, sq, off);
    }
    __shared__ float sm[8], sm2[8];
    const int warp = t >> 5, lane = t & 31;
    if (lane == 0) { sm[warp] = s; sm2[warp] = sq; }
    __syncthreads();
    float S = 0.f, SQ = 0.f;
    #pragma unroll
    for (int i = 0; i < 8; i++) { S += sm[i]; SQ += sm2[i]; }

    const float mu  = S * (1.f / (float)DD);
    const float var = SQ * (1.f / (float)DD) - mu * mu;
    const float inv = rsqrtf(var + 1e-5f);

    const float4* wv = (const float4*)w;
    const float4* bv = (const float4*)b;
    float4 w0 = wv[t], w1 = wv[t + 256];
    float4 b0 = bv[t], b1 = bv[t + 256];

    __nv_bfloat16* H = Xn + (size_t)row * DD;
    H[t*4+0] = __float2bfloat16((v0.x - mu) * inv * w0.x + b0.x);
    H[t*4+1] = __float2bfloat16((v0.y - mu) * inv * w0.y + b0.y);
    H[t*4+2] = __float2bfloat16((v0.z - mu) * inv * w0.z + b0.z);
    H[t*4+3] = __float2bfloat16((v0.w - mu) * inv * w0.w + b0.w);
    H[(t+256)*4+0] = __float2bfloat16((v1.x - mu) * inv * w1.x + b1.x);
    H[(t+256)*4+1] = __float2bfloat16((v1.y - mu) * inv * w1.y + b1.y);
    H[(t+256)*4+2] = __float2bfloat16((v1.z - mu) * inv * w1.z + b1.z);
    H[(t+256)*4+3] = __float2bfloat16((v1.w - mu) * inv * w1.w + b1.w);
}

// ---------------------------------------------------------------------------
// Kernel 2: weight transpose -> bf16.  W[2048][Ncols] fp32 -> Wt[Ncols][2048]
// ---------------------------------------------------------------------------
__global__ void __launch_bounds__(256) wsplit_kernel(
    const float* __restrict__ W, __nv_bfloat16* __restrict__ Wt, int Ncols)
{
    __shared__ float ts[32][33];
    const int tx = threadIdx.x & 31, ty = threadIdx.x >> 5;   // 32x8
    const int n0 = blockIdx.x * 32, k0 = blockIdx.y * 32;

    #pragma unroll
    for (int j = 0; j < 4; j++) {
        int r = ty + j * 8;
        ts[r][tx] = W[(size_t)(k0 + r) * Ncols + n0 + tx];
    }
    __syncthreads();
    #pragma unroll
    for (int j = 0; j < 4; j++) {
        int r = ty + j * 8;
        Wt[(size_t)(n0 + r) * GK + k0 + tx] = __float2bfloat16(ts[tx][r]);
    }
}

// ---------------------------------------------------------------------------
// GEMM core.  Tile 128x128, BK=64, 4 warps x (64x64), cp.async double buffer.
// Dynamic smem: 2 bufs x (As 128*ASTR + Bs 128*ASTR) bf16 = 73728 B.
// ---------------------------------------------------------------------------
#define BK    64
#define ASTR  72                       // 144B rows = 9x16B odd -> conflict-free ldmatrix
#define NCH   32                       // 2048 / 64
#define TILE_E (128 * ASTR)            // bf16 elems per tile buffer
#define GEMM_SMEM (4 * TILE_E * 2)     // bytes

#define GEMM_PROLOG() \
    extern __shared__ __nv_bfloat16 gsm[]; \
    __nv_bfloat16* Asb = gsm; \
    __nv_bfloat16* Bsb = gsm + 2 * TILE_E; \
    const int tid  = threadIdx.x; \
    const int wid  = tid >> 5, lane = tid & 31; \
    const int gid  = lane >> 2, tid2 = lane & 3; \
    const int wm   = wid & 1; \
    const int wn   = wid >> 1; \
    const int bm   = blockIdx.y * 128, bn = blockIdx.x * 128; \
    float acc[4][8][4]; \
    _Pragma("unroll") \
    for (int i = 0; i < 4; i++) \
        _Pragma("unroll") \
        for (int j = 0; j < 8; j++) \
            _Pragma("unroll") \
            for (int q = 0; q < 4; q++) acc[i][j][q] = 0.f; \
    const int a_row = wm * 64 + ((lane >> 3) & 1) * 8 + (lane & 7); \
    const int a_k   = (lane >> 4) * 8; \
    const int b_row = wn * 64 + ((lane >> 4) & 1) * 8 + (lane & 7); \
    const int b_k   = ((lane >> 3) & 1) * 8;

#define LOAD_TILES(buf, koff) do { \
    _Pragma("unroll") \
    for (int u = 0; u < 8; u++) { \
        int f = tid + u * 128; \
        int r = f >> 3, cb = (f & 7) * 8; \
        uint32_t da = (uint32_t)__cvta_generic_to_shared(&Asb[(buf) * TILE_E + r * ASTR + cb]); \
        CP_ASYNC16(da, A + (size_t)(bm + r) * GK + (koff) + cb); \
        uint32_t db = (uint32_t)__cvta_generic_to_shared(&Bsb[(buf) * TILE_E + r * ASTR + cb]); \
        CP_ASYNC16(db, B + (size_t)(bn + r) * GK + (koff) + cb); \
    } \
    CP_COMMIT(); \
} while (0)

#define GEMM_MAINLOOP() \
    LOAD_TILES(0, 0); \
    CP_WAIT0(); \
    __syncthreads(); \
    for (int kc = 0; kc < NCH; kc++) { \
        const int cur = kc & 1; \
        if (kc + 1 < NCH) LOAD_TILES((kc + 1) & 1, (kc + 1) * BK); \
        const __nv_bfloat16* Acur = Asb + cur * TILE_E; \
        const __nv_bfloat16* Bcur = Bsb + cur * TILE_E; \
        _Pragma("unroll") \
        for (int ks = 0; ks < BK; ks += 16) { \
            uint32_t af[4][4], bf_[8][2]; \
            _Pragma("unroll") \
            for (int mf = 0; mf < 4; mf++) { \
                uint32_t addr = (uint32_t)__cvta_generic_to_shared( \
                    (void*)&Acur[(a_row + mf * 16) * ASTR + ks + a_k]); \
                LDSM4(af[mf], addr); \
            } \
            _Pragma("unroll") \
            for (int np = 0; np < 4; np++) { \
                uint32_t r4[4]; \
                uint32_t addr = (uint32_t)__cvta_generic_to_shared( \
                    (void*)&Bcur[(b_row + np * 16) * ASTR + ks + b_k]); \
                LDSM4(r4, addr); \
                bf_[2*np][0]   = r4[0]; bf_[2*np][1]   = r4[1]; \
                bf_[2*np+1][0] = r4[2]; bf_[2*np+1][1] = r4[3]; \
            } \
            _Pragma("unroll") \
            for (int mf = 0; mf < 4; mf++) \
                _Pragma("unroll") \
                for (int nf = 0; nf < 8; nf++) \
                    MMA16816(acc[mf][nf], af[mf], bf_[nf]); \
        } \
        if (kc + 1 < NCH) CP_WAIT0(); \
        __syncthreads(); \
    }

// ---------------------------------------------------------------------------
// Kernel 3a: QKV GEMM with fused RoPE + bf16 conversion epilogue (MUFU math).
// ---------------------------------------------------------------------------
__global__ void __launch_bounds__(128, 2) mma_gemm_qkv(
    const __nv_bfloat16* __restrict__ A, const __nv_bfloat16* __restrict__ B,
    __nv_bfloat16* __restrict__ Qb, __nv_bfloat16* __restrict__ Kb,
    __nv_bfloat16* __restrict__ Vst)
{
    GEMM_PROLOG();
    GEMM_MAINLOOP();

    const float qs = 0.08838834764831845f * 1.4426950408889634f;

    #pragma unroll
    for (int nf = 0; nf < 8; nf++) {
        const int col  = bn + wn * 64 + nf * 8 + tid2 * 2;
        const int sec  = col >> 11;               // uniform per block
        const int rr   = col & 2047;
        const int head = rr >> 7;                 // uniform per block
        const int dcol = rr & 127;
        const bool rot = (dcol < 64);
        float invf = 0.f;
        if (rot)
            invf = __expf(-9.210340371976184f * ((float)(dcol >> 1) * (1.f / 32.f)));

        #pragma unroll
        for (int mf = 0; mf < 4; mf++) {
            #pragma unroll
            for (int half = 0; half < 2; half++) {
                const int row = bm + wm * 64 + mf * 16 + gid + half * 8;
                const int s   = row & (SS - 1);
                const int b   = row >> 11;
                float x1 = acc[mf][nf][half * 2];
                float x2 = acc[mf][nf][half * 2 + 1];

                if (sec < 2) {
                    if (rot) {
                        float sn, cs;
                        __sincosf((float)s * invf, &sn, &cs);
                        float r1 = x1 * cs - x2 * sn;
                        float r2 = x2 * cs + x1 * sn;
                        x1 = r1; x2 = r2;
                    }
                    if (sec == 0) { x1 *= qs; x2 *= qs; }
                    __nv_bfloat16* dst = (sec == 0) ? Qb : Kb;
                    *(uint32_t*)(dst + (((size_t)b * HH + head) * SS + s) * DH + dcol)
                        = pack_bf16x2(x1, x2);
                } else {
                    *(uint32_t*)(Vst + (size_t)row * DD + head * DH + dcol)
                        = pack_bf16x2(x1, x2);
                }
            }
        }
    }
}

// ---------------------------------------------------------------------------
// Kernel 3b: plain GEMM + residual (out projection), fp32 output.
// ---------------------------------------------------------------------------
__global__ void __launch_bounds__(128, 2) mma_gemm_out(
    const __nv_bfloat16* __restrict__ A, const __nv_bfloat16* __restrict__ B,
    const float* __restrict__ R, float* __restrict__ C, int N)
{
    GEMM_PROLOG();
    GEMM_MAINLOOP();

    #pragma unroll
    for (int mf = 0; mf < 4; mf++) {
        #pragma unroll
        for (int nf = 0; nf < 8; nf++) {
            const int row = bm + wm * 64 + mf * 16 + gid;
            const int col = bn + wn * 64 + nf * 8 + tid2 * 2;
            size_t o0 = (size_t)row * N + col;
            size_t o1 = (size_t)(row + 8) * N + col;
            float2 v0 = make_float2(acc[mf][nf][0], acc[mf][nf][1]);
            float2 v1 = make_float2(acc[mf][nf][2], acc[mf][nf][3]);
            float2 q0 = *(const float2*)(R + o0);
            float2 q1 = *(const float2*)(R + o1);
            v0.x += q0.x; v0.y += q0.y;
            v1.x += q1.x; v1.y += q1.y;
            *(float2*)(C + o0) = v0;
            *(float2*)(C + o1) = v1;
        }
    }
}

// ---------------------------------------------------------------------------
// Kernel 4: V staging bf16 -> bf16 transposed [b][h][d][s]
// ---------------------------------------------------------------------------
__global__ void __launch_bounds__(256) vconv_kernel(
    const __nv_bfloat16* __restrict__ Vst, __nv_bfloat16* __restrict__ Vt)
{
    __shared__ __nv_bfloat16 ts[32][33];
    const int tx = threadIdx.x & 31, ty = threadIdx.x >> 5;   // 32x8
    const int s0  = blockIdx.x * 32;
    const int hd0 = blockIdx.y * 32;          // h*128 + d0
    const int b   = blockIdx.z;

    #pragma unroll
    for (int j = 0; j < 4; j++) {
        int r = ty + j * 8;   // s offset
        ts[r][tx] = Vst[(size_t)(b * SS + s0 + r) * DD + hd0 + tx];
    }
    __syncthreads();
    #pragma unroll
    for (int j = 0; j < 4; j++) {
        int dt = ty + j * 8;  // d offset
        Vt[((size_t)b * HH * DH + hd0 + dt) * SS + s0 + tx] = ts[tx][dt];
    }
}

// ---------------------------------------------------------------------------
// Kernel 5: flash attention on mma.sync; cp.async double buffer; ldmatrix
// for K and V b-fragments (same lane mapping as GEMM B path).
// ---------------------------------------------------------------------------
#define AST 136
#define VST 72
#define ATTN_SMEM (2 * (64 * AST + 128 * VST) * 2)

__global__ void __launch_bounds__(128, 2) attn_mma(
    const __nv_bfloat16* __restrict__ Qb, const __nv_bfloat16* __restrict__ Kb,
    const __nv_bfloat16* __restrict__ Vt, __nv_bfloat16* __restrict__ ctx)
{
    extern __shared__ __nv_bfloat16 dsm[];
    __nv_bfloat16* KsBase = dsm;                   // 2 x 64*AST
    __nv_bfloat16* VsBase = dsm + 2 * 64 * AST;    // 2 x 128*VST

    const int tid = threadIdx.x, w = tid >> 5, lane = tid & 31;
    const int gid = lane >> 2, tid2 = lane & 3;
    const int qt = blockIdx.x, h = blockIdx.y, b = blockIdx.z;
    const int bh = b * HH + h;

    // ldmatrix lane mapping for B operands (same as GEMM)
    const int bl_row = ((lane >> 4) & 1) * 8 + (lane & 7);
    const int bl_k   = ((lane >> 3) & 1) * 8;

    const __nv_bfloat16* kgp = Kb + (size_t)bh * SS * DH;
    const __nv_bfloat16* vgp = Vt + (size_t)bh * DH * SS;

    #define ATTN_LOAD(buf, kt_) do { \
        __nv_bfloat16* Kd = KsBase + (buf) * 64 * AST; \
        __nv_bfloat16* Vd = VsBase + (buf) * 128 * VST; \
        _Pragma("unroll") \
        for (int u = 0; u < 8; u++) { \
            int f = tid + u * 128; \
            int r = f >> 4, c = (f & 15) * 8; \
            uint32_t d_ = (uint32_t)__cvta_generic_to_shared(&Kd[r * AST + c]); \
            CP_ASYNC16(d_, kgp + (size_t)((kt_) * 64 + r) * DH + c); \
        } \
        _Pragma("unroll") \
        for (int u = 0; u < 8; u++) { \
            int f = tid + u * 128; \
            int d2 = f >> 3, c = (f & 7) * 8; \
            uint32_t d_ = (uint32_t)__cvta_generic_to_shared(&Vd[d2 * VST + c]); \
            CP_ASYNC16(d_, vgp + (size_t)d2 * SS + (kt_) * 64 + c); \
        } \
        CP_COMMIT(); \
    } while (0)

    // Q fragments: 8 k-frags x 4 regs
    uint32_t qf[8][4];
    {
        const __nv_bfloat16* qp =
            Qb + ((size_t)bh * SS + qt * 64 + w * 16) * DH;
        #pragma unroll
        for (int kf = 0; kf < 8; kf++) {
            const __nv_bfloat16* p = qp + kf * 16 + tid2 * 2;
            qf[kf][0] = *(const uint32_t*)(p + (size_t)gid * DH);
            qf[kf][1] = *(const uint32_t*)(p + (size_t)(gid + 8) * DH);
            qf[kf][2] = *(const uint32_t*)(p + (size_t)gid * DH + 8);
            qf[kf][3] = *(const uint32_t*)(p + (size_t)(gid + 8) * DH + 8);
        }
    }

    float o[16][4];
    #pragma unroll
    for (int i = 0; i < 16; i++)
        #pragma unroll
        for (int q = 0; q < 4; q++) o[i][q] = 0.f;
    float m0 = -1e30f, m1 = -1e30f, l0 = 0.f, l1 = 0.f;

    ATTN_LOAD(0, 0);
    CP_WAIT0();
    __syncthreads();

    for (int kt = 0; kt < SS / 64; kt++) {
        const int cur = kt & 1;
        if (kt + 1 < SS / 64) ATTN_LOAD((kt + 1) & 1, kt + 1);

        const __nv_bfloat16* Ks = KsBase + cur * 64 * AST;
        const __nv_bfloat16* Vs = VsBase + cur * 128 * VST;

        // scores S[16 x 64] via ldmatrix B-frags
        float s[8][4];
        #pragma unroll
        for (int nf = 0; nf < 8; nf++)
            #pragma unroll
            for (int q = 0; q < 4; q++) s[nf][q] = 0.f;

        #pragma unroll
        for (int kf = 0; kf < 8; kf++) {
            #pragma unroll
            for (int np = 0; np < 4; np++) {
                uint32_t r4[4];
                uint32_t addr = (uint32_t)__cvta_generic_to_shared(
                    (void*)&Ks[(np * 16 + bl_row) * AST + kf * 16 + bl_k]);
                LDSM4(r4, addr);
                MMA16816(s[2*np],     qf[kf], r4);
                MMA16816(s[2*np + 1], qf[kf], r4 + 2);
            }
        }

        // online softmax (rows gid -> m0/l0, gid+8 -> m1/l1)
        float mx0 = -1e30f, mx1 = -1e30f;
        #pragma unroll
        for (int nf = 0; nf < 8; nf++) {
            mx0 = fmaxf(mx0, fmaxf(s[nf][0], s[nf][1]));
            mx1 = fmaxf(mx1, fmaxf(s[nf][2], s[nf][3]));
        }
        mx0 = fmaxf(mx0, __shfl_xor_sync(0xffffffffu, mx0, 1));
        mx0 = fmaxf(mx0, __shfl_xor_sync(0xffffffffu, mx0, 2));
        mx1 = fmaxf(mx1, __shfl_xor_sync(0xffffffffu, mx1, 1));
        mx1 = fmaxf(mx1, __shfl_xor_sync(0xffffffffu, mx1, 2));

        float nm0 = fmaxf(m0, mx0), nm1 = fmaxf(m1, mx1);
        float f0 = exp2_fast(m0 - nm0), f1 = exp2_fast(m1 - nm1);
        m0 = nm0; m1 = nm1;

        float sum0 = 0.f, sum1 = 0.f;
        #pragma unroll
        for (int nf = 0; nf < 8; nf++) {
            s[nf][0] = exp2_fast(s[nf][0] - m0);
            s[nf][1] = exp2_fast(s[nf][1] - m0);
            s[nf][2] = exp2_fast(s[nf][2] - m1);
            s[nf][3] = exp2_fast(s[nf][3] - m1);
            sum0 += s[nf][0] + s[nf][1];
            sum1 += s[nf][2] + s[nf][3];
        }
        sum0 += __shfl_xor_sync(0xffffffffu, sum0, 1);
        sum0 += __shfl_xor_sync(0xffffffffu, sum0, 2);
        sum1 += __shfl_xor_sync(0xffffffffu, sum1, 1);
        sum1 += __shfl_xor_sync(0xffffffffu, sum1, 2);
        l0 = l0 * f0 + sum0;
        l1 = l1 * f1 + sum1;

        #pragma unroll
        for (int nd = 0; nd < 16; nd++) {
            o[nd][0] *= f0; o[nd][1] *= f0;
            o[nd][2] *= f1; o[nd][3] *= f1;
        }

        // P @ V via ldmatrix B-frags
        #pragma unroll
        for (int kf2 = 0; kf2 < 4; kf2++) {
            uint32_t pa[4];
            pa[0] = pack_bf16x2(s[2*kf2][0],   s[2*kf2][1]);
            pa[1] = pack_bf16x2(s[2*kf2][2],   s[2*kf2][3]);
            pa[2] = pack_bf16x2(s[2*kf2+1][0], s[2*kf2+1][1]);
            pa[3] = pack_bf16x2(s[2*kf2+1][2], s[2*kf2+1][3]);
            #pragma unroll
            for (int np2 = 0; np2 < 8; np2++) {
                uint32_t r4[4];
                uint32_t addr = (uint32_t)__cvta_generic_to_shared(
                    (void*)&Vs[(np2 * 16 + bl_row) * VST + kf2 * 16 + bl_k]);
                LDSM4(r4, addr);
                MMA16816(o[2*np2],     pa, r4);
                MMA16816(o[2*np2 + 1], pa, r4 + 2);
            }
        }

        if (kt + 1 < SS / 64) CP_WAIT0();
        __syncthreads();
    }

    // epilogue: normalize, write ctx [row][h*128+d] bf16
    const float il0 = 1.f / l0, il1 = 1.f / l1;
    const size_t row0 = (size_t)(b * SS + qt * 64 + w * 16 + gid);
    __nv_bfloat16* cp0 = ctx + row0 * DD + h * DH + tid2 * 2;
    __nv_bfloat16* cp1 = cp0 + 8 * DD;
    #pragma unroll
    for (int nd = 0; nd < 16; nd++) {
        *(uint32_t*)(cp0 + nd * 8) = pack_bf16x2(o[nd][0] * il0, o[nd][1] * il0);
        *(uint32_t*)(cp1 + nd * 8) = pack_bf16x2(o[nd][2] * il1, o[nd][3] * il1);
    }
    #undef ATTN_LOAD
}

// ---------------------------------------------------------------------------
// Launch. Inputs: X, ln_w, ln_b, W_in, W_out. Output fp32.
// ---------------------------------------------------------------------------
extern "C" void kernel_launch(void* const* d_in, const int* in_sizes, int n_in,
                              void* d_out, int out_size)
{
    const float* X     = (const float*)d_in[0];
    const float* ln_w  = (const float*)d_in[1];
    const float* ln_b  = (const float*)d_in[2];
    const float* W_in  = (const float*)d_in[3];
    const float* W_out = (const float*)d_in[4];
    float*       out   = (float*)d_out;

    __nv_bfloat16 *pXn, *pWt, *pWoT, *pQb, *pKb, *pVst, *pVt, *pCtx;
    cudaGetSymbolAddress((void**)&pXn,  g_Xnb);
    cudaGetSymbolAddress((void**)&pWt,  g_Wt);
    cudaGetSymbolAddress((void**)&pWoT, g_WoT);
    cudaGetSymbolAddress((void**)&pQb,  g_Qb);
    cudaGetSymbolAddress((void**)&pKb,  g_Kb);
    cudaGetSymbolAddress((void**)&pVst, g_Vst);
    cudaGetSymbolAddress((void**)&pVt,  g_Vt);
    cudaGetSymbolAddress((void**)&pCtx, g_ctx);

    cudaFuncSetAttribute(attn_mma,
        cudaFuncAttributeMaxDynamicSharedMemorySize, ATTN_SMEM);
    cudaFuncSetAttribute(mma_gemm_qkv,
        cudaFuncAttributeMaxDynamicSharedMemorySize, GEMM_SMEM);
    cudaFuncSetAttribute(mma_gemm_out,
        cudaFuncAttributeMaxDynamicSharedMemorySize, GEMM_SMEM);

    // 0) Weight transpose -> bf16
    wsplit_kernel<<<dim3(NQKV / 32, DD / 32), 256>>>(W_in,  pWt,  NQKV);
    wsplit_kernel<<<dim3(DD   / 32, DD / 32), 256>>>(W_out, pWoT, DD);

    // 1) LayerNorm -> bf16
    ln_kernel<<<MM, 256>>>(X, ln_w, ln_b, pXn);

    // 2) QKV projection with fused RoPE + bf16 conversion (BK=64)
    mma_gemm_qkv<<<dim3(NQKV / 128, MM / 128), 128, GEMM_SMEM>>>(
        pXn, pWt, pQb, pKb, pVst);

    // 3) V transpose bf16 -> [b][h][d][s]
    vconv_kernel<<<dim3(SS / 32, HH * DH / 32, BB), 256>>>(pVst, pVt);

    // 4) Attention (tensor-core flash, cp.async + ldmatrix)
    attn_mma<<<dim3(SS / 64, HH, BB), 128, ATTN_SMEM>>>(pQb, pKb, pVt, pCtx);

    // 5) Output projection + residual (BK=64)
    mma_gemm_out<<<dim3(DD / 128, MM / 128), 128, GEMM_SMEM>>>(
        pCtx, pWoT, X, out, DD);
}